// round 14
// baseline (speedup 1.0000x reference)
#include <cuda_runtime.h>
#include <cstdint>
#include <math.h>

#define NN 50000
#define EE 800000
#define HD 128
#define KVB2 196
#define BAP 512
#define TCG 391
#define EPSI 1e-5f

__device__ __forceinline__ uint32_t f2tf32(float f){
    uint32_t r; asm("cvt.rna.tf32.f32 %0, %1;" : "=r"(r) : "f"(f)); return r;
}
__device__ __forceinline__ float rtf(float v){ return __uint_as_float(f2tf32(v)); }
__device__ __forceinline__ uint32_t smem_u32(const void* p){
    uint32_t a;
    asm("{ .reg .u64 t; cvta.to.shared.u64 t, %1; cvt.u32.u64 %0, t; }" : "=r"(a) : "l"(p));
    return a;
}
__device__ __forceinline__ void cp16(uint32_t dst, const float* src, bool pred){
    asm volatile("cp.async.cg.shared.global [%0], [%1], 16, %2;"
        :: "r"(dst), "l"(src), "r"(pred ? 16 : 0));
}
#define CP_COMMIT() asm volatile("cp.async.commit_group;" ::: "memory")
#define CP_WAIT1()  asm volatile("cp.async.wait_group 1;" ::: "memory")
#define CP_WAIT0()  asm volatile("cp.async.wait_group 0;" ::: "memory")

// ================= scratch =================
__device__ float g_h [NN*HD];
__device__ float g_z [NN*HD];
__device__ float g_q [NN*HD];
__device__ float g_k [NN*HD];
__device__ float g_p1[NN*HD];
__device__ float g_p2[NN*HD];
__device__ float g_p3[NN*HD];
__device__ float g_kvspart[KVB2*HD*HD];
__device__ float g_kvs[HD*HD];
__device__ float g_w0p[HD*HD];
__device__ float g_c0[HD];
__device__ float g_wt[15*16384];     // tf32-prerounded weights
__device__ float g_hpart[BAP*HD];
__device__ float g_kpart[TCG*HD];
__device__ float g_bns[TCG*HD];
__device__ float g_bnq[TCG*HD];
__device__ float g_ksum[HD];
__device__ float g_vsum[HD];
__device__ float g_scale[HD];
__device__ float g_shift[HD];
__device__ float g_zero[HD];         // zero-initialized, never written
__device__ float g_den[NN];
__device__ int   g_deg[NN];
__device__ float g_dis[NN];
__device__ int   g_indptr[NN+1];
__device__ int   g_cursor[NN];
__device__ int   g_arow[EE];
__device__ float g_aw[EE];

// ================= weight conversion (once per launch) =================
__global__ void cvt_weights(const float* __restrict__ Win, const float* __restrict__ Wq,
                            const float* __restrict__ Wk, const float* __restrict__ Wfc,
                            float* __restrict__ wt){
    int i = blockIdx.x*256 + threadIdx.x;      // 245760 total
    if(i >= 15*16384) return;
    float v;
    if(i < 16384)       v = Win[i];
    else if(i < 49152)  v = Wq[i - 16384];
    else if(i < 81920)  v = Wk[i - 49152];
    else                v = Wfc[i - 81920];
    wt[i] = rtf(v);
}

// ================= graph preprocessing =================
__global__ void deg_count(const int* __restrict__ col, int* __restrict__ deg){
    int e = blockIdx.x*blockDim.x + threadIdx.x;
    if(e < EE) atomicAdd(&deg[col[e]], 1);
}
__global__ void dis_kernel(const int* __restrict__ deg, float* __restrict__ dis){
    int i = blockIdx.x*blockDim.x + threadIdx.x;
    if(i < NN) dis[i] = deg[i] > 0 ? rsqrtf((float)deg[i]) : 0.0f;
}
__global__ void scan_kernel(const int* __restrict__ deg, int* __restrict__ indptr,
                            int* __restrict__ cursor){
    __shared__ int sh[1024];
    __shared__ int carry;
    int tid = threadIdx.x;
    if(tid == 0) carry = 0;
    __syncthreads();
    for(int base = 0; base < NN; base += 1024){
        int i = base + tid;
        int v = (i < NN) ? deg[i] : 0;
        sh[tid] = v; __syncthreads();
        for(int off = 1; off < 1024; off <<= 1){
            int t = (tid >= off) ? sh[tid-off] : 0;
            __syncthreads();
            sh[tid] += t;
            __syncthreads();
        }
        int incl = sh[tid];
        int c0 = carry;
        if(i < NN){ indptr[i] = c0 + incl - v; cursor[i] = c0 + incl - v; }
        __syncthreads();
        if(tid == 1023) carry = c0 + incl;
        __syncthreads();
    }
    if(tid == 1023) indptr[NN] = carry;
}
__global__ void csr_fill(const int* __restrict__ row, const int* __restrict__ col,
                         const float* __restrict__ dis, int* __restrict__ cursor,
                         int* __restrict__ arow, float* __restrict__ aw){
    int e = blockIdx.x*blockDim.x + threadIdx.x;
    if(e >= EE) return;
    int c = col[e], r = row[e];
    int p = atomicAdd(&cursor[c], 1);
    arow[p] = r;
    aw[p]   = dis[c] * dis[r];
}

// prop: out[c,:] = round_tf32( sum_j w_j * in[r_j,:] )
__global__ void prop_kernel(const int* __restrict__ indptr, const int* __restrict__ arow,
                            const float* __restrict__ aw, const float* __restrict__ in,
                            float* __restrict__ out){
    int n = blockIdx.x*8 + (threadIdx.x >> 5);
    if(n >= NN) return;
    int lane = threadIdx.x & 31;
    float4 acc = make_float4(0.f,0.f,0.f,0.f);
    int s = indptr[n], e = indptr[n+1];
    int j = s;
    for(; j + 1 < e; j += 2){
        int r0 = arow[j], r1 = arow[j+1];
        float w0 = aw[j], w1 = aw[j+1];
        float4 v0 = ((const float4*)(in + (size_t)r0*HD))[lane];
        float4 v1 = ((const float4*)(in + (size_t)r1*HD))[lane];
        acc.x += w0*v0.x + w1*v1.x; acc.y += w0*v0.y + w1*v1.y;
        acc.z += w0*v0.z + w1*v1.z; acc.w += w0*v0.w + w1*v1.w;
    }
    if(j < e){
        int r = arow[j]; float w = aw[j];
        float4 v = ((const float4*)(in + (size_t)r*HD))[lane];
        acc.x += w*v.x; acc.y += w*v.y; acc.z += w*v.z; acc.w += w*v.w;
    }
    acc.x = rtf(acc.x); acc.y = rtf(acc.y); acc.z = rtf(acc.z); acc.w = rtf(acc.w);
    ((float4*)(out + (size_t)n*HD))[lane] = acc;
}

// den[n] = dot(qn[n,:], ksum) + NN;  q[n,:] = round_tf32(q[n,:]/den[n])
__global__ void den_scale(float* __restrict__ q, const float* __restrict__ ksum,
                          float* __restrict__ den){
    int n = blockIdx.x*8 + (threadIdx.x >> 5);
    if(n >= NN) return;
    int lane = threadIdx.x & 31;
    float4* p = (float4*)(q + (size_t)n*HD);
    float4 v = p[lane];
    float4 k4 = ((const float4*)ksum)[lane];
    float d = v.x*k4.x + v.y*k4.y + v.z*k4.z + v.w*k4.w;
    #pragma unroll
    for(int o=16;o;o>>=1) d += __shfl_xor_sync(0xffffffffu, d, o);
    d += (float)NN;
    if(lane == 0) den[n] = d;
    float inv = 1.f/d;
    v.x = rtf(v.x*inv); v.y = rtf(v.y*inv); v.z = rtf(v.z*inv); v.w = rtf(v.w*inv);
    p[lane] = v;
}

// W0p = round_tf32(kvs @ W0), c0 = vsum @ W0 (fp32). Grid = 129.
__global__ void kvs_w0(const float* __restrict__ kvs, const float* __restrict__ vsum,
                       const float* __restrict__ W0,
                       float* __restrict__ W0p, float* __restrict__ c0){
    int m = blockIdx.x;
    int j = threadIdx.x;
    const float* rowp = (m < HD) ? (kvs + (size_t)m*HD) : vsum;
    float s = 0.f;
    #pragma unroll 4
    for(int d = 0; d < HD; d++) s += rowp[d] * __ldg(W0 + (size_t)d*HD + j);
    if(m < HD) W0p[(size_t)m*HD + j] = rtf(s);
    else       c0[j] = s;
}

// ================= tf32 mma.sync GEMM, pre-rounded operands ====
// MODE 2: C = acc + v1 + v2[col]/den[row] + res   (no reductions)
// MODE 3: C = round(rownorm(acc + v1)); cs[blk] = col partials
// MODE 5: C = acc + v1;          cs/cq[blk] = col sum / sumsq
// MODE 6: C = acc + v1 + res;    cs/cq[blk] = col sum / sumsq
// MODE 7: C = rownorm(acc + v1)  (norm only)
struct Parts  { const float* p[5]; };
struct PartsB { const float* p[5]; };

#define SA0 0
#define SA1 18432
#define SB0 36864
#define SB1 54272
#define SM_TOTAL 71680

template<int NPARTS, int MODE, int CVTA>
__global__ __launch_bounds__(256, 2)
void sgemm_mma(Parts parts, PartsB bparts,
               const float* __restrict__ v1, const float* __restrict__ v2,
               float* den, const float* __restrict__ res,
               float* __restrict__ C, float* __restrict__ cs, float* __restrict__ cq,
               int M){
    extern __shared__ char smem[];
    uint32_t sb = smem_u32(smem);
    int tid = threadIdx.x;
    int w = tid >> 5, lane = tid & 31;
    int g = lane >> 2, t = lane & 3;
    int m0 = (w & 3) * 32;
    int n0 = (w >> 2) * 64;
    int bm = blockIdx.x * 128;
    const int NCH = 4*NPARTS;

    float acc[2][8][4];
    #pragma unroll
    for(int mt=0;mt<2;mt++)
        #pragma unroll
        for(int nt=0;nt<8;nt++)
            #pragma unroll
            for(int i=0;i<4;i++) acc[mt][nt][i] = 0.f;

    auto prefetch = [&](int ch, int st){
        const float* A  = parts.p[ch>>2];
        const float* Bp = bparts.p[ch>>2];
        int kcc = ch & 3;
        uint32_t da = sb + (st ? SA1 : SA0);
        uint32_t db = sb + (st ? SB1 : SB0);
        #pragma unroll
        for(int it=0; it<4; ++it){
            int idx = tid + it*256;
            int r = idx >> 3, c4 = idx & 7;
            int gr = bm + r;
            int grc = (gr < M) ? gr : (M-1);
            cp16(da + (uint32_t)(r*36 + c4*4)*4,
                 A + (size_t)grc*HD + kcc*32 + c4*4, gr < M);
        }
        #pragma unroll
        for(int it=0; it<4; ++it){
            int idx = tid + it*256;
            int r = idx >> 5, c4 = idx & 31;
            cp16(db + (uint32_t)(r*136 + c4*4)*4,
                 Bp + (size_t)(kcc*32 + r)*HD + c4*4, true);
        }
    };

    prefetch(0, 0); CP_COMMIT();
    #pragma unroll 1
    for(int ch=0; ch<NCH; ++ch){
        int st = ch & 1;
        if(ch+1 < NCH){ prefetch(ch+1, st^1); CP_COMMIT(); CP_WAIT1(); }
        else CP_WAIT0();
        __syncthreads();
        const uint32_t* cA = (const uint32_t*)(smem + (st ? SA1 : SA0));
        const uint32_t* cB = (const uint32_t*)(smem + (st ? SB1 : SB0));
        #pragma unroll
        for(int ks=0; ks<4; ++ks){
            int k0 = ks*8;
            uint32_t a[2][4], b[8][2];
            #pragma unroll
            for(int mt=0;mt<2;mt++){
                int rb = m0 + mt*16 + g;
                a[mt][0] = cA[rb*36 + k0 + t];
                a[mt][1] = cA[(rb+8)*36 + k0 + t];
                a[mt][2] = cA[rb*36 + k0 + t + 4];
                a[mt][3] = cA[(rb+8)*36 + k0 + t + 4];
            }
            #pragma unroll
            for(int nt=0;nt<8;nt++){
                int nc = n0 + nt*8 + g;
                b[nt][0] = cB[(k0+t)*136 + nc];
                b[nt][1] = cB[(k0+t+4)*136 + nc];
            }
            if(CVTA){
                #pragma unroll
                for(int mt=0;mt<2;mt++)
                    #pragma unroll
                    for(int i=0;i<4;i++) a[mt][i] = f2tf32(__uint_as_float(a[mt][i]));
            }
            #pragma unroll
            for(int mt=0;mt<2;mt++){
                #pragma unroll
                for(int nt=0;nt<8;nt++){
                    asm volatile(
                        "mma.sync.aligned.m16n8k8.row.col.f32.tf32.tf32.f32 "
                        "{%0,%1,%2,%3}, {%4,%5,%6,%7}, {%8,%9}, {%0,%1,%2,%3};"
                        : "+f"(acc[mt][nt][0]), "+f"(acc[mt][nt][1]),
                          "+f"(acc[mt][nt][2]), "+f"(acc[mt][nt][3])
                        : "r"(a[mt][0]), "r"(a[mt][1]), "r"(a[mt][2]), "r"(a[mt][3]),
                          "r"(b[nt][0]), "r"(b[nt][1]));
                }
            }
        }
        __syncthreads();
    }

    // ---------- epilogue ----------
    float* sred  = (float*)smem;
    float* scol  = (float*)(smem + 2048);
    float* sqol  = (float*)(smem + 4096);

    float be[8][2];
    #pragma unroll
    for(int nt=0;nt<8;nt++){
        int c0i = n0 + nt*8 + 2*t;
        be[nt][0] = __ldg(v1 + c0i); be[nt][1] = __ldg(v1 + c0i + 1);
    }

    if(MODE == 2){
        float ce[8][2];
        #pragma unroll
        for(int nt=0;nt<8;nt++){
            int c0i = n0 + nt*8 + 2*t;
            ce[nt][0] = __ldg(v2 + c0i); ce[nt][1] = __ldg(v2 + c0i + 1);
        }
        #pragma unroll
        for(int mt=0;mt<2;mt++){
            int r1 = bm + m0 + mt*16 + g, r2 = r1 + 8;
            bool ok1 = r1 < M, ok2 = r2 < M;
            float i1 = ok1 ? 1.f/den[r1] : 0.f;
            float i2 = ok2 ? 1.f/den[r2] : 0.f;
            #pragma unroll
            for(int nt=0;nt<8;nt++){
                int cc = n0 + nt*8 + 2*t;
                float o0 = acc[mt][nt][0] + be[nt][0] + ce[nt][0]*i1;
                float o1 = acc[mt][nt][1] + be[nt][1] + ce[nt][1]*i1;
                float o2 = acc[mt][nt][2] + be[nt][0] + ce[nt][0]*i2;
                float o3 = acc[mt][nt][3] + be[nt][1] + ce[nt][1]*i2;
                if(ok1){
                    float2 rv = *(const float2*)(res + (size_t)r1*HD + cc);
                    o0 += rv.x; o1 += rv.y;
                    *(float2*)(C + (size_t)r1*HD + cc) = make_float2(o0, o1);
                }
                if(ok2){
                    float2 rv = *(const float2*)(res + (size_t)r2*HD + cc);
                    o2 += rv.x; o3 += rv.y;
                    *(float2*)(C + (size_t)r2*HD + cc) = make_float2(o2, o3);
                }
            }
        }
    } else if(MODE == 3 || MODE == 7){
        float ss[2][2] = {{0.f,0.f},{0.f,0.f}};
        #pragma unroll
        for(int mt=0;mt<2;mt++){
            #pragma unroll
            for(int nt=0;nt<8;nt++){
                float o0 = acc[mt][nt][0] + be[nt][0];
                float o1 = acc[mt][nt][1] + be[nt][1];
                float o2 = acc[mt][nt][2] + be[nt][0];
                float o3 = acc[mt][nt][3] + be[nt][1];
                acc[mt][nt][0]=o0; acc[mt][nt][1]=o1; acc[mt][nt][2]=o2; acc[mt][nt][3]=o3;
                ss[mt][0] += o0*o0 + o1*o1;
                ss[mt][1] += o2*o2 + o3*o3;
            }
        }
        #pragma unroll
        for(int off=1; off<=2; off<<=1){
            #pragma unroll
            for(int mt=0;mt<2;mt++){
                ss[mt][0] += __shfl_xor_sync(0xffffffffu, ss[mt][0], off);
                ss[mt][1] += __shfl_xor_sync(0xffffffffu, ss[mt][1], off);
            }
        }
        int half = w >> 2;
        if(t == 0){
            #pragma unroll
            for(int mt=0;mt<2;mt++){
                sred[half*128 + m0 + mt*16 + g]     = ss[mt][0];
                sred[half*128 + m0 + mt*16 + g + 8] = ss[mt][1];
            }
        }
        __syncthreads();
        float inv[2][2];
        #pragma unroll
        for(int mt=0;mt<2;mt++){
            #pragma unroll
            for(int j=0;j<2;j++){
                int rl = m0 + mt*16 + g + j*8;
                inv[mt][j] = rsqrtf(sred[rl] + sred[128 + rl]);
            }
        }
        float ca[8][2];
        #pragma unroll
        for(int nt=0;nt<8;nt++){ ca[nt][0]=0.f; ca[nt][1]=0.f; }
        #pragma unroll
        for(int mt=0;mt<2;mt++){
            int r1 = bm + m0 + mt*16 + g, r2 = r1 + 8;
            bool ok1 = r1 < M, ok2 = r2 < M;
            #pragma unroll
            for(int nt=0;nt<8;nt++){
                int cc = n0 + nt*8 + 2*t;
                float o0 = acc[mt][nt][0]*inv[mt][0];
                float o1 = acc[mt][nt][1]*inv[mt][0];
                float o2 = acc[mt][nt][2]*inv[mt][1];
                float o3 = acc[mt][nt][3]*inv[mt][1];
                if(MODE == 3){   // k feeds kvs_mma: store pre-rounded
                    o0 = rtf(o0); o1 = rtf(o1); o2 = rtf(o2); o3 = rtf(o3);
                }
                if(ok1) *(float2*)(C + (size_t)r1*HD + cc) = make_float2(o0, o1);
                if(ok2) *(float2*)(C + (size_t)r2*HD + cc) = make_float2(o2, o3);
                if(MODE == 3){
                    ca[nt][0] += (ok1?o0:0.f) + (ok2?o2:0.f);
                    ca[nt][1] += (ok1?o1:0.f) + (ok2?o3:0.f);
                }
            }
        }
        if(MODE == 3){
            #pragma unroll
            for(int off=4; off<=16; off<<=1)
                #pragma unroll
                for(int nt=0;nt<8;nt++){
                    ca[nt][0] += __shfl_xor_sync(0xffffffffu, ca[nt][0], off);
                    ca[nt][1] += __shfl_xor_sync(0xffffffffu, ca[nt][1], off);
                }
            if(lane < 4){
                #pragma unroll
                for(int nt=0;nt<8;nt++){
                    scol[w*64 + nt*8 + 2*t]     = ca[nt][0];
                    scol[w*64 + nt*8 + 2*t + 1] = ca[nt][1];
                }
            }
            __syncthreads();
            if(tid < 128){
                int c = tid, hf = c >> 6, cl = c & 63;
                float s = 0.f;
                #pragma unroll
                for(int j=0;j<4;j++) s += scol[(hf*4+j)*64 + cl];
                cs[blockIdx.x*HD + c] = s;
            }
        }
    } else { // MODE 5 / 6
        float ca[8][2], cqv[8][2];
        #pragma unroll
        for(int nt=0;nt<8;nt++){ ca[nt][0]=0.f; ca[nt][1]=0.f; cqv[nt][0]=0.f; cqv[nt][1]=0.f; }
        #pragma unroll
        for(int mt=0;mt<2;mt++){
            int r1 = bm + m0 + mt*16 + g, r2 = r1 + 8;
            bool ok1 = r1 < M, ok2 = r2 < M;
            #pragma unroll
            for(int nt=0;nt<8;nt++){
                int cc = n0 + nt*8 + 2*t;
                float o0 = acc[mt][nt][0] + be[nt][0];
                float o1 = acc[mt][nt][1] + be[nt][1];
                float o2 = acc[mt][nt][2] + be[nt][0];
                float o3 = acc[mt][nt][3] + be[nt][1];
                if(MODE == 6){
                    if(ok1){
                        float2 rv = *(const float2*)(res + (size_t)r1*HD + cc);
                        o0 += rv.x; o1 += rv.y;
                    }
                    if(ok2){
                        float2 rv = *(const float2*)(res + (size_t)r2*HD + cc);
                        o2 += rv.x; o3 += rv.y;
                    }
                }
                if(ok1) *(float2*)(C + (size_t)r1*HD + cc) = make_float2(o0, o1);
                if(ok2) *(float2*)(C + (size_t)r2*HD + cc) = make_float2(o2, o3);
                ca[nt][0]  += (ok1?o0:0.f) + (ok2?o2:0.f);
                ca[nt][1]  += (ok1?o1:0.f) + (ok2?o3:0.f);
                cqv[nt][0] += (ok1?o0*o0:0.f) + (ok2?o2*o2:0.f);
                cqv[nt][1] += (ok1?o1*o1:0.f) + (ok2?o3*o3:0.f);
            }
        }
        #pragma unroll
        for(int off=4; off<=16; off<<=1)
            #pragma unroll
            for(int nt=0;nt<8;nt++){
                ca[nt][0]  += __shfl_xor_sync(0xffffffffu, ca[nt][0], off);
                ca[nt][1]  += __shfl_xor_sync(0xffffffffu, ca[nt][1], off);
                cqv[nt][0] += __shfl_xor_sync(0xffffffffu, cqv[nt][0], off);
                cqv[nt][1] += __shfl_xor_sync(0xffffffffu, cqv[nt][1], off);
            }
        if(lane < 4){
            #pragma unroll
            for(int nt=0;nt<8;nt++){
                scol[w*64 + nt*8 + 2*t]     = ca[nt][0];
                scol[w*64 + nt*8 + 2*t + 1] = ca[nt][1];
                sqol[w*64 + nt*8 + 2*t]     = cqv[nt][0];
                sqol[w*64 + nt*8 + 2*t + 1] = cqv[nt][1];
            }
        }
        __syncthreads();
        if(tid < 128){
            int c = tid, hf = c >> 6, cl = c & 63;
            float s = 0.f, qq = 0.f;
            #pragma unroll
            for(int j=0;j<4;j++){ s += scol[(hf*4+j)*64 + cl]; qq += sqol[(hf*4+j)*64 + cl]; }
            cs[blockIdx.x*HD + c] = s;
            cq[blockIdx.x*HD + c] = qq;
        }
    }
}

// ================= kvs via tensor cores (inputs pre-rounded) =================
#define KV_SA 0
#define KV_SB 34816
#define KV_SMEM 69632

__global__ __launch_bounds__(256, 2)
void kvs_mma(const float* __restrict__ kn, const float* __restrict__ vv,
             float* __restrict__ part){
    extern __shared__ char smem[];
    float* sA = (float*)(smem + KV_SA);
    float* sB = (float*)(smem + KV_SB);
    int tid = threadIdx.x;
    int w = tid >> 5, lane = tid & 31;
    int g = lane >> 2, t = lane & 3;
    int m0 = (w & 3) * 32;
    int n0 = (w >> 2) * 64;
    int base = blockIdx.x * 256;

    float acc[2][8][4];
    #pragma unroll
    for(int mt=0;mt<2;mt++)
        #pragma unroll
        for(int nt=0;nt<8;nt++)
            #pragma unroll
            for(int i=0;i<4;i++) acc[mt][nt][i] = 0.f;

    #pragma unroll 1
    for(int sub=0; sub<4; ++sub){
        int nb = base + sub*64;
        #pragma unroll
        for(int it=0; it<8; ++it){
            int idx = tid + it*256;
            int r = idx >> 5, c4 = idx & 31;
            int gn = nb + r;
            bool ok = gn < NN;
            float4 ka = ok ? ((const float4*)(kn + (size_t)gn*HD))[c4] : make_float4(0,0,0,0);
            float4 va = ok ? ((const float4*)(vv + (size_t)gn*HD))[c4] : make_float4(0,0,0,0);
            *(float4*)(sA + r*136 + c4*4) = ka;
            *(float4*)(sB + r*136 + c4*4) = va;
        }
        __syncthreads();
        #pragma unroll
        for(int ks=0; ks<8; ++ks){
            int k0 = ks*8;
            uint32_t a[2][4], b[8][2];
            const uint32_t* uA = (const uint32_t*)sA;
            const uint32_t* uB = (const uint32_t*)sB;
            #pragma unroll
            for(int mt=0;mt<2;mt++){
                int rb = m0 + mt*16 + g;
                a[mt][0] = uA[(k0+t)*136 + rb];
                a[mt][1] = uA[(k0+t)*136 + rb + 8];
                a[mt][2] = uA[(k0+t+4)*136 + rb];
                a[mt][3] = uA[(k0+t+4)*136 + rb + 8];
            }
            #pragma unroll
            for(int nt=0;nt<8;nt++){
                int nc = n0 + nt*8 + g;
                b[nt][0] = uB[(k0+t)*136 + nc];
                b[nt][1] = uB[(k0+t+4)*136 + nc];
            }
            #pragma unroll
            for(int mt=0;mt<2;mt++){
                #pragma unroll
                for(int nt=0;nt<8;nt++){
                    asm volatile(
                        "mma.sync.aligned.m16n8k8.row.col.f32.tf32.tf32.f32 "
                        "{%0,%1,%2,%3}, {%4,%5,%6,%7}, {%8,%9}, {%0,%1,%2,%3};"
                        : "+f"(acc[mt][nt][0]), "+f"(acc[mt][nt][1]),
                          "+f"(acc[mt][nt][2]), "+f"(acc[mt][nt][3])
                        : "r"(a[mt][0]), "r"(a[mt][1]), "r"(a[mt][2]), "r"(a[mt][3]),
                          "r"(b[nt][0]), "r"(b[nt][1]));
                }
            }
        }
        __syncthreads();
    }

    float* P = part + (size_t)blockIdx.x*HD*HD;
    #pragma unroll
    for(int mt=0;mt<2;mt++){
        int r1 = m0 + mt*16 + g;
        int r2 = r1 + 8;
        #pragma unroll
        for(int nt=0;nt<8;nt++){
            int cc = n0 + nt*8 + 2*t;
            *(float2*)(P + (size_t)r1*HD + cc) = make_float2(acc[mt][nt][0], acc[mt][nt][1]);
            *(float2*)(P + (size_t)r2*HD + cc) = make_float2(acc[mt][nt][2], acc[mt][nt][3]);
        }
    }
}

__global__ void kvs_reduce(const float* __restrict__ part, float* __restrict__ kvs){
    int i = blockIdx.x*blockDim.x + threadIdx.x;
    if(i >= HD*HD) return;
    float s = 0.f;
    for(int b=0;b<KVB2;b++) s += part[(size_t)b*HD*HD + i];
    kvs[i] = s;
}

// ================= parallel small reductions =================
__global__ void colsum_reduce(const float* __restrict__ part, float* __restrict__ out,
                              int count){
    __shared__ float sh[8][128];
    int c = threadIdx.x & 127, sl = threadIdx.x >> 7;
    float s = 0.f;
    for(int b = sl; b < count; b += 8) s += part[b*HD + c];
    sh[sl][c] = s;
    __syncthreads();
    if(threadIdx.x < 128){
        float tot = 0.f;
        #pragma unroll
        for(int j=0;j<8;j++) tot += sh[j][c];
        out[c] = tot;
    }
}

__global__ void bn_finish(const float* __restrict__ ps, const float* __restrict__ pq,
                          const float* __restrict__ g, const float* __restrict__ b,
                          float* __restrict__ scale, float* __restrict__ shift,
                          int count){
    __shared__ float shs[8][128], shq[8][128];
    int c = threadIdx.x & 127, sl = threadIdx.x >> 7;
    float s = 0.f, q = 0.f;
    for(int i = sl; i < count; i += 8){ s += ps[i*HD+c]; q += pq[i*HD+c]; }
    shs[sl][c] = s; shq[sl][c] = q;
    __syncthreads();
    if(threadIdx.x < 128){
        float ts = 0.f, tq = 0.f;
        #pragma unroll
        for(int j=0;j<8;j++){ ts += shs[j][c]; tq += shq[j][c]; }
        float mean = ts / (float)NN;
        float var  = tq / (float)NN - mean*mean;
        float sc = g[c] * rsqrtf(var + EPSI);
        scale[c] = sc;
        shift[c] = b[c] - mean*sc;
    }
}

__global__ void bn_apply_relu(const float* __restrict__ z, const float* __restrict__ scale,
                              const float* __restrict__ shift, float* __restrict__ h,
                              float* __restrict__ hpart){
    int c = threadIdx.x;
    int b = blockIdx.x;
    int chunk = (NN + BAP - 1)/BAP;
    int r0 = b*chunk, r1 = min(NN, r0 + chunk);
    float sc = scale[c], sh = shift[c];
    float s = 0.f;
    int r = r0;
    for(; r + 3 < r1; r += 4){
        float v0 = rtf(fmaxf(z[(size_t)(r+0)*HD + c]*sc + sh, 0.f));
        float v1 = rtf(fmaxf(z[(size_t)(r+1)*HD + c]*sc + sh, 0.f));
        float v2 = rtf(fmaxf(z[(size_t)(r+2)*HD + c]*sc + sh, 0.f));
        float v3 = rtf(fmaxf(z[(size_t)(r+3)*HD + c]*sc + sh, 0.f));
        h[(size_t)(r+0)*HD + c] = v0; h[(size_t)(r+1)*HD + c] = v1;
        h[(size_t)(r+2)*HD + c] = v2; h[(size_t)(r+3)*HD + c] = v3;
        s += v0 + v1 + v2 + v3;
    }
    for(; r < r1; ++r){
        float v = rtf(fmaxf(z[(size_t)r*HD + c]*sc + sh, 0.f));
        h[(size_t)r*HD + c] = v; s += v;
    }
    hpart[b*HD + c] = s;
}

__global__ void out_gemm(const float* __restrict__ h, const float* __restrict__ W,
                         const float* __restrict__ b, float* __restrict__ out){
    int n = blockIdx.x*8 + (threadIdx.x >> 5);
    if(n >= NN) return;
    int lane = threadIdx.x & 31;
    const float* hr = h + (size_t)n*HD;
    float acc0 = 0.f, acc1 = 0.f;
    #pragma unroll 8
    for(int k4=0;k4<32;k4++){
        float4 hv = ((const float4*)hr)[k4];
        int k = k4*4;
        acc0 += hv.x*__ldg(W + (k+0)*40 + lane);
        acc0 += hv.y*__ldg(W + (k+1)*40 + lane);
        acc0 += hv.z*__ldg(W + (k+2)*40 + lane);
        acc0 += hv.w*__ldg(W + (k+3)*40 + lane);
        if(lane < 8){
            acc1 += hv.x*__ldg(W + (k+0)*40 + 32 + lane);
            acc1 += hv.y*__ldg(W + (k+1)*40 + 32 + lane);
            acc1 += hv.z*__ldg(W + (k+2)*40 + 32 + lane);
            acc1 += hv.w*__ldg(W + (k+3)*40 + 32 + lane);
        }
    }
    out[(size_t)n*40 + lane] = acc0 + b[lane];
    if(lane < 8) out[(size_t)n*40 + 32 + lane] = acc1 + b[32 + lane];
}

// ================= host =================
extern "C" void kernel_launch(void* const* d_in, const int* in_sizes, int n_in,
                              void* d_out, int out_size){
    const float* x     = (const float*)d_in[0];
    const int*   ei    = (const int*)  d_in[1];
    const float* W_in  = (const float*)d_in[2];
    const float* b_in  = (const float*)d_in[3];
    const float* Wq    = (const float*)d_in[4];
    const float* bq    = (const float*)d_in[5];
    const float* Wk    = (const float*)d_in[6];
    const float* bk    = (const float*)d_in[7];
    const float* Wfc   = (const float*)d_in[8];
    const float* bfc   = (const float*)d_in[9];
    const float* W_out = (const float*)d_in[10];
    const float* b_out = (const float*)d_in[11];
    const float* bn_g  = (const float*)d_in[12];
    const float* bn_b  = (const float*)d_in[13];
    float* out = (float*)d_out;

    const int* row = ei;
    const int* col = ei + EE;

    float *h,*z,*q,*k,*p1,*p2,*p3,*kvspart,*kvs,*w0p,*c0,*wt,*hpart,*kpart,*bns,*bnq;
    float *ksum,*vsum,*scale,*shift,*zerov,*den,*dis,*aw;
    int *deg,*indptr,*cursor,*arow;
    cudaGetSymbolAddress((void**)&h,  g_h);
    cudaGetSymbolAddress((void**)&z,  g_z);
    cudaGetSymbolAddress((void**)&q,  g_q);
    cudaGetSymbolAddress((void**)&k,  g_k);
    cudaGetSymbolAddress((void**)&p1, g_p1);
    cudaGetSymbolAddress((void**)&p2, g_p2);
    cudaGetSymbolAddress((void**)&p3, g_p3);
    cudaGetSymbolAddress((void**)&kvspart, g_kvspart);
    cudaGetSymbolAddress((void**)&kvs, g_kvs);
    cudaGetSymbolAddress((void**)&w0p, g_w0p);
    cudaGetSymbolAddress((void**)&c0,  g_c0);
    cudaGetSymbolAddress((void**)&wt,  g_wt);
    cudaGetSymbolAddress((void**)&hpart, g_hpart);
    cudaGetSymbolAddress((void**)&kpart, g_kpart);
    cudaGetSymbolAddress((void**)&bns, g_bns);
    cudaGetSymbolAddress((void**)&bnq, g_bnq);
    cudaGetSymbolAddress((void**)&ksum, g_ksum);
    cudaGetSymbolAddress((void**)&vsum, g_vsum);
    cudaGetSymbolAddress((void**)&scale, g_scale);
    cudaGetSymbolAddress((void**)&shift, g_shift);
    cudaGetSymbolAddress((void**)&zerov, g_zero);
    cudaGetSymbolAddress((void**)&den, g_den);
    cudaGetSymbolAddress((void**)&dis, g_dis);
    cudaGetSymbolAddress((void**)&aw,  g_aw);
    cudaGetSymbolAddress((void**)&deg, g_deg);
    cudaGetSymbolAddress((void**)&indptr, g_indptr);
    cudaGetSymbolAddress((void**)&cursor, g_cursor);
    cudaGetSymbolAddress((void**)&arow, g_arow);

    const float* wtWin = wt;
    const float* wtWq  = wt + 16384;
    const float* wtWk  = wt + 49152;
    const float* wtWfc = wt + 81920;

    cudaFuncSetAttribute(sgemm_mma<2,2,0>, cudaFuncAttributeMaxDynamicSharedMemorySize, SM_TOTAL);
    cudaFuncSetAttribute(sgemm_mma<1,3,0>, cudaFuncAttributeMaxDynamicSharedMemorySize, SM_TOTAL);
    cudaFuncSetAttribute(sgemm_mma<1,5,1>, cudaFuncAttributeMaxDynamicSharedMemorySize, SM_TOTAL);
    cudaFuncSetAttribute(sgemm_mma<3,6,0>, cudaFuncAttributeMaxDynamicSharedMemorySize, SM_TOTAL);
    cudaFuncSetAttribute(sgemm_mma<1,7,0>, cudaFuncAttributeMaxDynamicSharedMemorySize, SM_TOTAL);
    cudaFuncSetAttribute(kvs_mma, cudaFuncAttributeMaxDynamicSharedMemorySize, KV_SMEM);

    const int WARP_GRID = (NN + 7)/8;

    static cudaStream_t s1 = nullptr, s2 = nullptr;
    static cudaEvent_t e0, e1, eF[2], eK[2], eS1[2], eW[2];
    if(s1 == nullptr){
        cudaStreamCreateWithFlags(&s1, cudaStreamNonBlocking);
        cudaStreamCreateWithFlags(&s2, cudaStreamNonBlocking);
        cudaEventCreateWithFlags(&e0, cudaEventDisableTiming);
        cudaEventCreateWithFlags(&e1, cudaEventDisableTiming);
        for(int i=0;i<2;i++){
            cudaEventCreateWithFlags(&eF[i],  cudaEventDisableTiming);
            cudaEventCreateWithFlags(&eK[i],  cudaEventDisableTiming);
            cudaEventCreateWithFlags(&eS1[i], cudaEventDisableTiming);
            cudaEventCreateWithFlags(&eW[i],  cudaEventDisableTiming);
        }
    }

    // ---- fork: graph preprocessing on s1; weight cvt + input layer on stream 0 ----
    cudaEventRecord(e0, 0);
    cudaStreamWaitEvent(s1, e0, 0);
    cudaMemsetAsync(deg, 0, NN*sizeof(int), s1);
    deg_count<<<(EE+255)/256, 256, 0, s1>>>(col, deg);
    dis_kernel<<<(NN+255)/256, 256, 0, s1>>>(deg, dis);
    scan_kernel<<<1, 1024, 0, s1>>>(deg, indptr, cursor);
    csr_fill<<<(EE+255)/256, 256, 0, s1>>>(row, col, dis, cursor, arow, aw);
    cudaEventRecord(e1, s1);

    cvt_weights<<<(15*16384+255)/256, 256>>>(W_in, Wq, Wk, Wfc, wt);
    {
        Parts P; P.p[0]=x; P.p[1]=0; P.p[2]=0; P.p[3]=0; P.p[4]=0;
        PartsB B; B.p[0]=wtWin; B.p[1]=0; B.p[2]=0; B.p[3]=0; B.p[4]=0;
        sgemm_mma<1,5,1><<<TCG,256,SM_TOTAL>>>(P, B, b_in, nullptr, nullptr, nullptr,
                                               z, bns, bnq, NN);
        bn_finish<<<1,1024>>>(bns, bnq, bn_g + 0*HD, bn_b + 0*HD, scale, shift, TCG);
        bn_apply_relu<<<BAP,HD>>>(z, scale, shift, h, hpart);
    }

    for(int i=0;i<2;i++){
        Parts Ph; Ph.p[0]=h; Ph.p[1]=0; Ph.p[2]=0; Ph.p[3]=0; Ph.p[4]=0;
        const float* Wfci = Wfc + (size_t)i*640*HD;           // original (for kvs_w0)
        const float* wtWfci = wtWfc + (size_t)i*640*HD;       // pre-rounded

        cudaEventRecord(eF[i], 0);
        cudaStreamWaitEvent(s1, eF[i], 0);
        cudaStreamWaitEvent(s2, eF[i], 0);

        // ---- s1: vsum, k-GEMM -> ksum -> kvs -> W0p/c0 ----
        colsum_reduce<<<1,1024,0,s1>>>(hpart, vsum, BAP);
        {
            PartsB Bk; Bk.p[0]=wtWk + (size_t)i*HD*HD; Bk.p[1]=0; Bk.p[2]=0; Bk.p[3]=0; Bk.p[4]=0;
            sgemm_mma<1,3,0><<<TCG,256,SM_TOTAL,s1>>>(Ph, Bk, bk + i*HD, nullptr, nullptr,
                                                      nullptr, k, kpart, nullptr, NN);
        }
        colsum_reduce<<<1,1024,0,s1>>>(kpart, ksum, TCG);
        cudaEventRecord(eK[i], s1);
        kvs_mma<<<KVB2,256,KV_SMEM,s1>>>(k, h, kvspart);
        kvs_reduce<<<(HD*HD+255)/256,256,0,s1>>>(kvspart, kvs);
        kvs_w0<<<HD+1,HD,0,s1>>>(kvs, vsum, Wfci, w0p, c0);
        cudaEventRecord(eS1[i], s1);

        // ---- s2: q-GEMM -> den/scale -> Wfc part A (q@W0p + h@W1 + bias + c0/den + h) ----
        {
            PartsB Bq; Bq.p[0]=wtWq + (size_t)i*HD*HD; Bq.p[1]=0; Bq.p[2]=0; Bq.p[3]=0; Bq.p[4]=0;
            sgemm_mma<1,7,0><<<TCG,256,SM_TOTAL,s2>>>(Ph, Bq, bq + i*HD, nullptr, nullptr,
                                                      nullptr, q, nullptr, nullptr, NN);
        }
        cudaStreamWaitEvent(s2, eK[i], 0);
        den_scale<<<WARP_GRID,256,0,s2>>>(q, ksum, den);
        cudaStreamWaitEvent(s2, eS1[i], 0);
        {
            Parts P2; P2.p[0]=q; P2.p[1]=h; P2.p[2]=0; P2.p[3]=0; P2.p[4]=0;
            PartsB B2; B2.p[0]=w0p; B2.p[1]=wtWfci + 1*HD*HD; B2.p[2]=0; B2.p[3]=0; B2.p[4]=0;
            sgemm_mma<2,2,0><<<TCG,256,SM_TOTAL,s2>>>(P2, B2, bfc + i*HD, c0, den, h,
                                                      z, nullptr, nullptr, NN);
        }
        cudaEventRecord(eW[i], s2);

        // ---- s0: prop chain ----
        if(i == 0) cudaStreamWaitEvent(0, e1, 0);
        prop_kernel<<<WARP_GRID,256>>>(indptr, arow, aw, h,  p1);
        prop_kernel<<<WARP_GRID,256>>>(indptr, arow, aw, p1, p2);
        prop_kernel<<<WARP_GRID,256>>>(indptr, arow, aw, p2, p3);

        // ---- join: Wfc part B (z += [p1,p2,p3]@W2..4) + BN partials ----
        cudaStreamWaitEvent(0, eW[i], 0);
        {
            Parts P3; P3.p[0]=p1; P3.p[1]=p2; P3.p[2]=p3; P3.p[3]=0; P3.p[4]=0;
            PartsB B3; B3.p[0]=wtWfci + 2*HD*HD; B3.p[1]=wtWfci + 3*HD*HD;
            B3.p[2]=wtWfci + 4*HD*HD; B3.p[3]=0; B3.p[4]=0;
            sgemm_mma<3,6,0><<<TCG,256,SM_TOTAL>>>(P3, B3, zerov, nullptr, nullptr, z,
                                                   z, bns, bnq, NN);
        }
        bn_finish<<<1,1024>>>(bns, bnq, bn_g + (i+1)*HD, bn_b + (i+1)*HD, scale, shift, TCG);
        bn_apply_relu<<<BAP,HD>>>(z, scale, shift, h, hpart);
    }

    out_gemm<<<WARP_GRID,256>>>(h, W_out, b_out, out);
}

// round 15
// speedup vs baseline: 1.4831x; 1.4831x over previous
#include <cuda_runtime.h>
#include <cstdint>
#include <math.h>

#define NN 50000
#define EE 800000
#define HD 128
#define KVB2 196
#define BAP 512
#define TCG 391
#define EPSI 1e-5f

__device__ __forceinline__ uint32_t f2tf32(float f){
    uint32_t r; asm("cvt.rna.tf32.f32 %0, %1;" : "=r"(r) : "f"(f)); return r;
}
__device__ __forceinline__ float rtf(float v){ return __uint_as_float(f2tf32(v)); }
__device__ __forceinline__ uint32_t smem_u32(const void* p){
    uint32_t a;
    asm("{ .reg .u64 t; cvta.to.shared.u64 t, %1; cvt.u32.u64 %0, t; }" : "=r"(a) : "l"(p));
    return a;
}
__device__ __forceinline__ void cp16(uint32_t dst, const float* src, bool pred){
    asm volatile("cp.async.cg.shared.global [%0], [%1], 16, %2;"
        :: "r"(dst), "l"(src), "r"(pred ? 16 : 0));
}
#define CP_COMMIT() asm volatile("cp.async.commit_group;" ::: "memory")
#define CP_WAIT1()  asm volatile("cp.async.wait_group 1;" ::: "memory")
#define CP_WAIT0()  asm volatile("cp.async.wait_group 0;" ::: "memory")

// ================= scratch =================
__device__ float g_h [NN*HD];
__device__ float g_z [NN*HD];
__device__ float g_q [NN*HD];
__device__ float g_k [NN*HD];
__device__ float g_p1[NN*HD];
__device__ float g_p2[NN*HD];
__device__ float g_p3[NN*HD];
__device__ float g_kvspart[KVB2*HD*HD];
__device__ float g_kvs[HD*HD];
__device__ float g_w0p[HD*HD];
__device__ float g_c0[HD];
__device__ float g_wt[15*16384];     // tf32-prerounded weights
__device__ float g_hpart[BAP*HD];
__device__ float g_kpart[TCG*HD];
__device__ float g_bns[TCG*HD];
__device__ float g_bnq[TCG*HD];
__device__ float g_ksum[HD];
__device__ float g_vsum[HD];
__device__ float g_scale[HD];
__device__ float g_shift[HD];
__device__ float g_den[NN];
__device__ int   g_deg[NN];
__device__ float g_dis[NN];
__device__ int   g_indptr[NN+1];
__device__ int   g_cursor[NN];
__device__ int   g_arow[EE];
__device__ float g_aw[EE];

// ================= weight conversion (once per launch) =================
__global__ void cvt_weights(const float* __restrict__ Win, const float* __restrict__ Wq,
                            const float* __restrict__ Wk, const float* __restrict__ Wfc,
                            float* __restrict__ wt){
    int i = blockIdx.x*256 + threadIdx.x;      // 245760 total
    if(i >= 15*16384) return;
    float v;
    if(i < 16384)       v = Win[i];
    else if(i < 49152)  v = Wq[i - 16384];
    else if(i < 81920)  v = Wk[i - 49152];
    else                v = Wfc[i - 81920];
    wt[i] = rtf(v);
}

// ================= graph preprocessing =================
__global__ void deg_count(const int* __restrict__ col, int* __restrict__ deg){
    int e = blockIdx.x*blockDim.x + threadIdx.x;
    if(e < EE) atomicAdd(&deg[col[e]], 1);
}
__global__ void dis_kernel(const int* __restrict__ deg, float* __restrict__ dis){
    int i = blockIdx.x*blockDim.x + threadIdx.x;
    if(i < NN) dis[i] = deg[i] > 0 ? rsqrtf((float)deg[i]) : 0.0f;
}
__global__ void scan_kernel(const int* __restrict__ deg, int* __restrict__ indptr,
                            int* __restrict__ cursor){
    __shared__ int sh[1024];
    __shared__ int carry;
    int tid = threadIdx.x;
    if(tid == 0) carry = 0;
    __syncthreads();
    for(int base = 0; base < NN; base += 1024){
        int i = base + tid;
        int v = (i < NN) ? deg[i] : 0;
        sh[tid] = v; __syncthreads();
        for(int off = 1; off < 1024; off <<= 1){
            int t = (tid >= off) ? sh[tid-off] : 0;
            __syncthreads();
            sh[tid] += t;
            __syncthreads();
        }
        int incl = sh[tid];
        int c0 = carry;
        if(i < NN){ indptr[i] = c0 + incl - v; cursor[i] = c0 + incl - v; }
        __syncthreads();
        if(tid == 1023) carry = c0 + incl;
        __syncthreads();
    }
    if(tid == 1023) indptr[NN] = carry;
}
__global__ void csr_fill(const int* __restrict__ row, const int* __restrict__ col,
                         const float* __restrict__ dis, int* __restrict__ cursor,
                         int* __restrict__ arow, float* __restrict__ aw){
    int e = blockIdx.x*blockDim.x + threadIdx.x;
    if(e >= EE) return;
    int c = col[e], r = row[e];
    int p = atomicAdd(&cursor[c], 1);
    arow[p] = r;
    aw[p]   = dis[c] * dis[r];
}

// prop: out[c,:] = round_tf32( sum_j w_j * in[r_j,:] )
__global__ void prop_kernel(const int* __restrict__ indptr, const int* __restrict__ arow,
                            const float* __restrict__ aw, const float* __restrict__ in,
                            float* __restrict__ out){
    int n = blockIdx.x*8 + (threadIdx.x >> 5);
    if(n >= NN) return;
    int lane = threadIdx.x & 31;
    float4 acc = make_float4(0.f,0.f,0.f,0.f);
    int s = indptr[n], e = indptr[n+1];
    int j = s;
    for(; j + 1 < e; j += 2){
        int r0 = arow[j], r1 = arow[j+1];
        float w0 = aw[j], w1 = aw[j+1];
        float4 v0 = ((const float4*)(in + (size_t)r0*HD))[lane];
        float4 v1 = ((const float4*)(in + (size_t)r1*HD))[lane];
        acc.x += w0*v0.x + w1*v1.x; acc.y += w0*v0.y + w1*v1.y;
        acc.z += w0*v0.z + w1*v1.z; acc.w += w0*v0.w + w1*v1.w;
    }
    if(j < e){
        int r = arow[j]; float w = aw[j];
        float4 v = ((const float4*)(in + (size_t)r*HD))[lane];
        acc.x += w*v.x; acc.y += w*v.y; acc.z += w*v.z; acc.w += w*v.w;
    }
    acc.x = rtf(acc.x); acc.y = rtf(acc.y); acc.z = rtf(acc.z); acc.w = rtf(acc.w);
    ((float4*)(out + (size_t)n*HD))[lane] = acc;
}

// den[n] = dot(qn[n,:], ksum) + NN;  q[n,:] = round_tf32(q[n,:]/den[n])
__global__ void den_scale(float* __restrict__ q, const float* __restrict__ ksum,
                          float* __restrict__ den){
    int n = blockIdx.x*8 + (threadIdx.x >> 5);
    if(n >= NN) return;
    int lane = threadIdx.x & 31;
    float4* p = (float4*)(q + (size_t)n*HD);
    float4 v = p[lane];
    float4 k4 = ((const float4*)ksum)[lane];
    float d = v.x*k4.x + v.y*k4.y + v.z*k4.z + v.w*k4.w;
    #pragma unroll
    for(int o=16;o;o>>=1) d += __shfl_xor_sync(0xffffffffu, d, o);
    d += (float)NN;
    if(lane == 0) den[n] = d;
    float inv = 1.f/d;
    v.x = rtf(v.x*inv); v.y = rtf(v.y*inv); v.z = rtf(v.z*inv); v.w = rtf(v.w*inv);
    p[lane] = v;
}

// W0p = round_tf32(kvs @ W0), c0 = vsum @ W0 (fp32). Grid = 129.
__global__ void kvs_w0(const float* __restrict__ kvs, const float* __restrict__ vsum,
                       const float* __restrict__ W0,
                       float* __restrict__ W0p, float* __restrict__ c0){
    int m = blockIdx.x;
    int j = threadIdx.x;
    const float* rowp = (m < HD) ? (kvs + (size_t)m*HD) : vsum;
    float s = 0.f;
    #pragma unroll 4
    for(int d = 0; d < HD; d++) s += rowp[d] * __ldg(W0 + (size_t)d*HD + j);
    if(m < HD) W0p[(size_t)m*HD + j] = rtf(s);
    else       c0[j] = s;
}

// ================= tf32 mma.sync GEMM, pre-rounded operands ====
// MODE 3: C = round(rownorm(acc + v1)); cs[blk] = col partials
// MODE 5: C = acc + v1;          cs/cq[blk] = col sum / sumsq
// MODE 7: C = rownorm(acc + v1)  (norm only)
// MODE 8: C = acc + v1 + res + v2[col]/den[row]; cs/cq[blk]
struct Parts  { const float* p[5]; };
struct PartsB { const float* p[5]; };

#define SA0 0
#define SA1 18432
#define SB0 36864
#define SB1 54272
#define SM_TOTAL 71680

template<int NPARTS, int MODE, int CVTA>
__global__ __launch_bounds__(256, 2)
void sgemm_mma(Parts parts, PartsB bparts,
               const float* __restrict__ v1, const float* __restrict__ v2,
               float* den, const float* __restrict__ res,
               float* __restrict__ C, float* __restrict__ cs, float* __restrict__ cq,
               int M){
    extern __shared__ char smem[];
    uint32_t sb = smem_u32(smem);
    int tid = threadIdx.x;
    int w = tid >> 5, lane = tid & 31;
    int g = lane >> 2, t = lane & 3;
    int m0 = (w & 3) * 32;
    int n0 = (w >> 2) * 64;
    int bm = blockIdx.x * 128;
    const int NCH = 4*NPARTS;

    float acc[2][8][4];
    #pragma unroll
    for(int mt=0;mt<2;mt++)
        #pragma unroll
        for(int nt=0;nt<8;nt++)
            #pragma unroll
            for(int i=0;i<4;i++) acc[mt][nt][i] = 0.f;

    auto prefetch = [&](int ch, int st){
        const float* A  = parts.p[ch>>2];
        const float* Bp = bparts.p[ch>>2];
        int kcc = ch & 3;
        uint32_t da = sb + (st ? SA1 : SA0);
        uint32_t db = sb + (st ? SB1 : SB0);
        #pragma unroll
        for(int it=0; it<4; ++it){
            int idx = tid + it*256;
            int r = idx >> 3, c4 = idx & 7;
            int gr = bm + r;
            int grc = (gr < M) ? gr : (M-1);
            cp16(da + (uint32_t)(r*36 + c4*4)*4,
                 A + (size_t)grc*HD + kcc*32 + c4*4, gr < M);
        }
        #pragma unroll
        for(int it=0; it<4; ++it){
            int idx = tid + it*256;
            int r = idx >> 5, c4 = idx & 31;
            cp16(db + (uint32_t)(r*136 + c4*4)*4,
                 Bp + (size_t)(kcc*32 + r)*HD + c4*4, true);
        }
    };

    prefetch(0, 0); CP_COMMIT();
    #pragma unroll 1
    for(int ch=0; ch<NCH; ++ch){
        int st = ch & 1;
        if(ch+1 < NCH){ prefetch(ch+1, st^1); CP_COMMIT(); CP_WAIT1(); }
        else CP_WAIT0();
        __syncthreads();
        const uint32_t* cA = (const uint32_t*)(smem + (st ? SA1 : SA0));
        const uint32_t* cB = (const uint32_t*)(smem + (st ? SB1 : SB0));
        #pragma unroll
        for(int ks=0; ks<4; ++ks){
            int k0 = ks*8;
            uint32_t a[2][4], b[8][2];
            #pragma unroll
            for(int mt=0;mt<2;mt++){
                int rb = m0 + mt*16 + g;
                a[mt][0] = cA[rb*36 + k0 + t];
                a[mt][1] = cA[(rb+8)*36 + k0 + t];
                a[mt][2] = cA[rb*36 + k0 + t + 4];
                a[mt][3] = cA[(rb+8)*36 + k0 + t + 4];
            }
            #pragma unroll
            for(int nt=0;nt<8;nt++){
                int nc = n0 + nt*8 + g;
                b[nt][0] = cB[(k0+t)*136 + nc];
                b[nt][1] = cB[(k0+t+4)*136 + nc];
            }
            if(CVTA){
                #pragma unroll
                for(int mt=0;mt<2;mt++)
                    #pragma unroll
                    for(int i=0;i<4;i++) a[mt][i] = f2tf32(__uint_as_float(a[mt][i]));
            }
            #pragma unroll
            for(int mt=0;mt<2;mt++){
                #pragma unroll
                for(int nt=0;nt<8;nt++){
                    asm volatile(
                        "mma.sync.aligned.m16n8k8.row.col.f32.tf32.tf32.f32 "
                        "{%0,%1,%2,%3}, {%4,%5,%6,%7}, {%8,%9}, {%0,%1,%2,%3};"
                        : "+f"(acc[mt][nt][0]), "+f"(acc[mt][nt][1]),
                          "+f"(acc[mt][nt][2]), "+f"(acc[mt][nt][3])
                        : "r"(a[mt][0]), "r"(a[mt][1]), "r"(a[mt][2]), "r"(a[mt][3]),
                          "r"(b[nt][0]), "r"(b[nt][1]));
                }
            }
        }
        __syncthreads();
    }

    // ---------- epilogue ----------
    float* sred  = (float*)smem;
    float* scol  = (float*)(smem + 2048);
    float* sqol  = (float*)(smem + 4096);

    float be[8][2];
    #pragma unroll
    for(int nt=0;nt<8;nt++){
        int c0i = n0 + nt*8 + 2*t;
        be[nt][0] = __ldg(v1 + c0i); be[nt][1] = __ldg(v1 + c0i + 1);
    }

    if(MODE == 3 || MODE == 7){
        float ss[2][2] = {{0.f,0.f},{0.f,0.f}};
        #pragma unroll
        for(int mt=0;mt<2;mt++){
            #pragma unroll
            for(int nt=0;nt<8;nt++){
                float o0 = acc[mt][nt][0] + be[nt][0];
                float o1 = acc[mt][nt][1] + be[nt][1];
                float o2 = acc[mt][nt][2] + be[nt][0];
                float o3 = acc[mt][nt][3] + be[nt][1];
                acc[mt][nt][0]=o0; acc[mt][nt][1]=o1; acc[mt][nt][2]=o2; acc[mt][nt][3]=o3;
                ss[mt][0] += o0*o0 + o1*o1;
                ss[mt][1] += o2*o2 + o3*o3;
            }
        }
        #pragma unroll
        for(int off=1; off<=2; off<<=1){
            #pragma unroll
            for(int mt=0;mt<2;mt++){
                ss[mt][0] += __shfl_xor_sync(0xffffffffu, ss[mt][0], off);
                ss[mt][1] += __shfl_xor_sync(0xffffffffu, ss[mt][1], off);
            }
        }
        int half = w >> 2;
        if(t == 0){
            #pragma unroll
            for(int mt=0;mt<2;mt++){
                sred[half*128 + m0 + mt*16 + g]     = ss[mt][0];
                sred[half*128 + m0 + mt*16 + g + 8] = ss[mt][1];
            }
        }
        __syncthreads();
        float inv[2][2];
        #pragma unroll
        for(int mt=0;mt<2;mt++){
            #pragma unroll
            for(int j=0;j<2;j++){
                int rl = m0 + mt*16 + g + j*8;
                inv[mt][j] = rsqrtf(sred[rl] + sred[128 + rl]);
            }
        }
        float ca[8][2];
        #pragma unroll
        for(int nt=0;nt<8;nt++){ ca[nt][0]=0.f; ca[nt][1]=0.f; }
        #pragma unroll
        for(int mt=0;mt<2;mt++){
            int r1 = bm + m0 + mt*16 + g, r2 = r1 + 8;
            bool ok1 = r1 < M, ok2 = r2 < M;
            #pragma unroll
            for(int nt=0;nt<8;nt++){
                int cc = n0 + nt*8 + 2*t;
                float o0 = acc[mt][nt][0]*inv[mt][0];
                float o1 = acc[mt][nt][1]*inv[mt][0];
                float o2 = acc[mt][nt][2]*inv[mt][1];
                float o3 = acc[mt][nt][3]*inv[mt][1];
                if(MODE == 3){   // k feeds kvs_mma: store pre-rounded
                    o0 = rtf(o0); o1 = rtf(o1); o2 = rtf(o2); o3 = rtf(o3);
                }
                if(ok1) *(float2*)(C + (size_t)r1*HD + cc) = make_float2(o0, o1);
                if(ok2) *(float2*)(C + (size_t)r2*HD + cc) = make_float2(o2, o3);
                if(MODE == 3){
                    ca[nt][0] += (ok1?o0:0.f) + (ok2?o2:0.f);
                    ca[nt][1] += (ok1?o1:0.f) + (ok2?o3:0.f);
                }
            }
        }
        if(MODE == 3){
            #pragma unroll
            for(int off=4; off<=16; off<<=1)
                #pragma unroll
                for(int nt=0;nt<8;nt++){
                    ca[nt][0] += __shfl_xor_sync(0xffffffffu, ca[nt][0], off);
                    ca[nt][1] += __shfl_xor_sync(0xffffffffu, ca[nt][1], off);
                }
            if(lane < 4){
                #pragma unroll
                for(int nt=0;nt<8;nt++){
                    scol[w*64 + nt*8 + 2*t]     = ca[nt][0];
                    scol[w*64 + nt*8 + 2*t + 1] = ca[nt][1];
                }
            }
            __syncthreads();
            if(tid < 128){
                int c = tid, hf = c >> 6, cl = c & 63;
                float s = 0.f;
                #pragma unroll
                for(int j=0;j<4;j++) s += scol[(hf*4+j)*64 + cl];
                cs[blockIdx.x*HD + c] = s;
            }
        }
    } else { // MODE 5 / 8
        float ce[8][2];
        if(MODE == 8){
            #pragma unroll
            for(int nt=0;nt<8;nt++){
                int c0i = n0 + nt*8 + 2*t;
                ce[nt][0] = __ldg(v2 + c0i); ce[nt][1] = __ldg(v2 + c0i + 1);
            }
        }
        float ca[8][2], cqv[8][2];
        #pragma unroll
        for(int nt=0;nt<8;nt++){ ca[nt][0]=0.f; ca[nt][1]=0.f; cqv[nt][0]=0.f; cqv[nt][1]=0.f; }
        #pragma unroll
        for(int mt=0;mt<2;mt++){
            int r1 = bm + m0 + mt*16 + g, r2 = r1 + 8;
            bool ok1 = r1 < M, ok2 = r2 < M;
            float i1 = 0.f, i2 = 0.f;
            if(MODE == 8){
                if(ok1) i1 = 1.f/den[r1];
                if(ok2) i2 = 1.f/den[r2];
            }
            #pragma unroll
            for(int nt=0;nt<8;nt++){
                int cc = n0 + nt*8 + 2*t;
                float o0 = acc[mt][nt][0] + be[nt][0];
                float o1 = acc[mt][nt][1] + be[nt][1];
                float o2 = acc[mt][nt][2] + be[nt][0];
                float o3 = acc[mt][nt][3] + be[nt][1];
                if(MODE == 8){
                    o0 += ce[nt][0]*i1; o1 += ce[nt][1]*i1;
                    o2 += ce[nt][0]*i2; o3 += ce[nt][1]*i2;
                    if(ok1){
                        float2 rv = *(const float2*)(res + (size_t)r1*HD + cc);
                        o0 += rv.x; o1 += rv.y;
                    }
                    if(ok2){
                        float2 rv = *(const float2*)(res + (size_t)r2*HD + cc);
                        o2 += rv.x; o3 += rv.y;
                    }
                }
                if(ok1) *(float2*)(C + (size_t)r1*HD + cc) = make_float2(o0, o1);
                if(ok2) *(float2*)(C + (size_t)r2*HD + cc) = make_float2(o2, o3);
                ca[nt][0]  += (ok1?o0:0.f) + (ok2?o2:0.f);
                ca[nt][1]  += (ok1?o1:0.f) + (ok2?o3:0.f);
                cqv[nt][0] += (ok1?o0*o0:0.f) + (ok2?o2*o2:0.f);
                cqv[nt][1] += (ok1?o1*o1:0.f) + (ok2?o3*o3:0.f);
            }
        }
        #pragma unroll
        for(int off=4; off<=16; off<<=1)
            #pragma unroll
            for(int nt=0;nt<8;nt++){
                ca[nt][0]  += __shfl_xor_sync(0xffffffffu, ca[nt][0], off);
                ca[nt][1]  += __shfl_xor_sync(0xffffffffu, ca[nt][1], off);
                cqv[nt][0] += __shfl_xor_sync(0xffffffffu, cqv[nt][0], off);
                cqv[nt][1] += __shfl_xor_sync(0xffffffffu, cqv[nt][1], off);
            }
        if(lane < 4){
            #pragma unroll
            for(int nt=0;nt<8;nt++){
                scol[w*64 + nt*8 + 2*t]     = ca[nt][0];
                scol[w*64 + nt*8 + 2*t + 1] = ca[nt][1];
                sqol[w*64 + nt*8 + 2*t]     = cqv[nt][0];
                sqol[w*64 + nt*8 + 2*t + 1] = cqv[nt][1];
            }
        }
        __syncthreads();
        if(tid < 128){
            int c = tid, hf = c >> 6, cl = c & 63;
            float s = 0.f, qq = 0.f;
            #pragma unroll
            for(int j=0;j<4;j++){ s += scol[(hf*4+j)*64 + cl]; qq += sqol[(hf*4+j)*64 + cl]; }
            cs[blockIdx.x*HD + c] = s;
            cq[blockIdx.x*HD + c] = qq;
        }
    }
}

// ================= kvs via tensor cores (inputs pre-rounded) =================
#define KV_SA 0
#define KV_SB 34816
#define KV_SMEM 69632

__global__ __launch_bounds__(256, 2)
void kvs_mma(const float* __restrict__ kn, const float* __restrict__ vv,
             float* __restrict__ part){
    extern __shared__ char smem[];
    float* sA = (float*)(smem + KV_SA);
    float* sB = (float*)(smem + KV_SB);
    int tid = threadIdx.x;
    int w = tid >> 5, lane = tid & 31;
    int g = lane >> 2, t = lane & 3;
    int m0 = (w & 3) * 32;
    int n0 = (w >> 2) * 64;
    int base = blockIdx.x * 256;

    float acc[2][8][4];
    #pragma unroll
    for(int mt=0;mt<2;mt++)
        #pragma unroll
        for(int nt=0;nt<8;nt++)
            #pragma unroll
            for(int i=0;i<4;i++) acc[mt][nt][i] = 0.f;

    #pragma unroll 1
    for(int sub=0; sub<4; ++sub){
        int nb = base + sub*64;
        #pragma unroll
        for(int it=0; it<8; ++it){
            int idx = tid + it*256;
            int r = idx >> 5, c4 = idx & 31;
            int gn = nb + r;
            bool ok = gn < NN;
            float4 ka = ok ? ((const float4*)(kn + (size_t)gn*HD))[c4] : make_float4(0,0,0,0);
            float4 va = ok ? ((const float4*)(vv + (size_t)gn*HD))[c4] : make_float4(0,0,0,0);
            *(float4*)(sA + r*136 + c4*4) = ka;
            *(float4*)(sB + r*136 + c4*4) = va;
        }
        __syncthreads();
        #pragma unroll
        for(int ks=0; ks<8; ++ks){
            int k0 = ks*8;
            uint32_t a[2][4], b[8][2];
            const uint32_t* uA = (const uint32_t*)sA;
            const uint32_t* uB = (const uint32_t*)sB;
            #pragma unroll
            for(int mt=0;mt<2;mt++){
                int rb = m0 + mt*16 + g;
                a[mt][0] = uA[(k0+t)*136 + rb];
                a[mt][1] = uA[(k0+t)*136 + rb + 8];
                a[mt][2] = uA[(k0+t+4)*136 + rb];
                a[mt][3] = uA[(k0+t+4)*136 + rb + 8];
            }
            #pragma unroll
            for(int nt=0;nt<8;nt++){
                int nc = n0 + nt*8 + g;
                b[nt][0] = uB[(k0+t)*136 + nc];
                b[nt][1] = uB[(k0+t+4)*136 + nc];
            }
            #pragma unroll
            for(int mt=0;mt<2;mt++){
                #pragma unroll
                for(int nt=0;nt<8;nt++){
                    asm volatile(
                        "mma.sync.aligned.m16n8k8.row.col.f32.tf32.tf32.f32 "
                        "{%0,%1,%2,%3}, {%4,%5,%6,%7}, {%8,%9}, {%0,%1,%2,%3};"
                        : "+f"(acc[mt][nt][0]), "+f"(acc[mt][nt][1]),
                          "+f"(acc[mt][nt][2]), "+f"(acc[mt][nt][3])
                        : "r"(a[mt][0]), "r"(a[mt][1]), "r"(a[mt][2]), "r"(a[mt][3]),
                          "r"(b[nt][0]), "r"(b[nt][1]));
                }
            }
        }
        __syncthreads();
    }

    float* P = part + (size_t)blockIdx.x*HD*HD;
    #pragma unroll
    for(int mt=0;mt<2;mt++){
        int r1 = m0 + mt*16 + g;
        int r2 = r1 + 8;
        #pragma unroll
        for(int nt=0;nt<8;nt++){
            int cc = n0 + nt*8 + 2*t;
            *(float2*)(P + (size_t)r1*HD + cc) = make_float2(acc[mt][nt][0], acc[mt][nt][1]);
            *(float2*)(P + (size_t)r2*HD + cc) = make_float2(acc[mt][nt][2], acc[mt][nt][3]);
        }
    }
}

__global__ void kvs_reduce(const float* __restrict__ part, float* __restrict__ kvs){
    int i = blockIdx.x*blockDim.x + threadIdx.x;
    if(i >= HD*HD) return;
    float s = 0.f;
    for(int b=0;b<KVB2;b++) s += part[(size_t)b*HD*HD + i];
    kvs[i] = s;
}

// ================= parallel small reductions =================
__global__ void colsum_reduce(const float* __restrict__ part, float* __restrict__ out,
                              int count){
    __shared__ float sh[8][128];
    int c = threadIdx.x & 127, sl = threadIdx.x >> 7;
    float s = 0.f;
    for(int b = sl; b < count; b += 8) s += part[b*HD + c];
    sh[sl][c] = s;
    __syncthreads();
    if(threadIdx.x < 128){
        float tot = 0.f;
        #pragma unroll
        for(int j=0;j<8;j++) tot += sh[j][c];
        out[c] = tot;
    }
}

__global__ void bn_finish(const float* __restrict__ ps, const float* __restrict__ pq,
                          const float* __restrict__ g, const float* __restrict__ b,
                          float* __restrict__ scale, float* __restrict__ shift,
                          int count){
    __shared__ float shs[8][128], shq[8][128];
    int c = threadIdx.x & 127, sl = threadIdx.x >> 7;
    float s = 0.f, q = 0.f;
    for(int i = sl; i < count; i += 8){ s += ps[i*HD+c]; q += pq[i*HD+c]; }
    shs[sl][c] = s; shq[sl][c] = q;
    __syncthreads();
    if(threadIdx.x < 128){
        float ts = 0.f, tq = 0.f;
        #pragma unroll
        for(int j=0;j<8;j++){ ts += shs[j][c]; tq += shq[j][c]; }
        float mean = ts / (float)NN;
        float var  = tq / (float)NN - mean*mean;
        float sc = g[c] * rsqrtf(var + EPSI);
        scale[c] = sc;
        shift[c] = b[c] - mean*sc;
    }
}

__global__ void bn_apply_relu(const float* __restrict__ z, const float* __restrict__ scale,
                              const float* __restrict__ shift, float* __restrict__ h,
                              float* __restrict__ hpart){
    int c = threadIdx.x;
    int b = blockIdx.x;
    int chunk = (NN + BAP - 1)/BAP;
    int r0 = b*chunk, r1 = min(NN, r0 + chunk);
    float sc = scale[c], sh = shift[c];
    float s = 0.f;
    int r = r0;
    for(; r + 3 < r1; r += 4){
        float v0 = rtf(fmaxf(z[(size_t)(r+0)*HD + c]*sc + sh, 0.f));
        float v1 = rtf(fmaxf(z[(size_t)(r+1)*HD + c]*sc + sh, 0.f));
        float v2 = rtf(fmaxf(z[(size_t)(r+2)*HD + c]*sc + sh, 0.f));
        float v3 = rtf(fmaxf(z[(size_t)(r+3)*HD + c]*sc + sh, 0.f));
        h[(size_t)(r+0)*HD + c] = v0; h[(size_t)(r+1)*HD + c] = v1;
        h[(size_t)(r+2)*HD + c] = v2; h[(size_t)(r+3)*HD + c] = v3;
        s += v0 + v1 + v2 + v3;
    }
    for(; r < r1; ++r){
        float v = rtf(fmaxf(z[(size_t)r*HD + c]*sc + sh, 0.f));
        h[(size_t)r*HD + c] = v; s += v;
    }
    hpart[b*HD + c] = s;
}

__global__ void out_gemm(const float* __restrict__ h, const float* __restrict__ W,
                         const float* __restrict__ b, float* __restrict__ out){
    int n = blockIdx.x*8 + (threadIdx.x >> 5);
    if(n >= NN) return;
    int lane = threadIdx.x & 31;
    const float* hr = h + (size_t)n*HD;
    float acc0 = 0.f, acc1 = 0.f;
    #pragma unroll 8
    for(int k4=0;k4<32;k4++){
        float4 hv = ((const float4*)hr)[k4];
        int k = k4*4;
        acc0 += hv.x*__ldg(W + (k+0)*40 + lane);
        acc0 += hv.y*__ldg(W + (k+1)*40 + lane);
        acc0 += hv.z*__ldg(W + (k+2)*40 + lane);
        acc0 += hv.w*__ldg(W + (k+3)*40 + lane);
        if(lane < 8){
            acc1 += hv.x*__ldg(W + (k+0)*40 + 32 + lane);
            acc1 += hv.y*__ldg(W + (k+1)*40 + 32 + lane);
            acc1 += hv.z*__ldg(W + (k+2)*40 + 32 + lane);
            acc1 += hv.w*__ldg(W + (k+3)*40 + 32 + lane);
        }
    }
    out[(size_t)n*40 + lane] = acc0 + b[lane];
    if(lane < 8) out[(size_t)n*40 + 32 + lane] = acc1 + b[32 + lane];
}

// ================= host =================
extern "C" void kernel_launch(void* const* d_in, const int* in_sizes, int n_in,
                              void* d_out, int out_size){
    const float* x     = (const float*)d_in[0];
    const int*   ei    = (const int*)  d_in[1];
    const float* W_in  = (const float*)d_in[2];
    const float* b_in  = (const float*)d_in[3];
    const float* Wq    = (const float*)d_in[4];
    const float* bq    = (const float*)d_in[5];
    const float* Wk    = (const float*)d_in[6];
    const float* bk    = (const float*)d_in[7];
    const float* Wfc   = (const float*)d_in[8];
    const float* bfc   = (const float*)d_in[9];
    const float* W_out = (const float*)d_in[10];
    const float* b_out = (const float*)d_in[11];
    const float* bn_g  = (const float*)d_in[12];
    const float* bn_b  = (const float*)d_in[13];
    float* out = (float*)d_out;

    const int* row = ei;
    const int* col = ei + EE;

    float *h,*z,*q,*k,*p1,*p2,*p3,*kvspart,*kvs,*w0p,*c0,*wt,*hpart,*kpart,*bns,*bnq;
    float *ksum,*vsum,*scale,*shift,*den,*dis,*aw;
    int *deg,*indptr,*cursor,*arow;
    cudaGetSymbolAddress((void**)&h,  g_h);
    cudaGetSymbolAddress((void**)&z,  g_z);
    cudaGetSymbolAddress((void**)&q,  g_q);
    cudaGetSymbolAddress((void**)&k,  g_k);
    cudaGetSymbolAddress((void**)&p1, g_p1);
    cudaGetSymbolAddress((void**)&p2, g_p2);
    cudaGetSymbolAddress((void**)&p3, g_p3);
    cudaGetSymbolAddress((void**)&kvspart, g_kvspart);
    cudaGetSymbolAddress((void**)&kvs, g_kvs);
    cudaGetSymbolAddress((void**)&w0p, g_w0p);
    cudaGetSymbolAddress((void**)&c0,  g_c0);
    cudaGetSymbolAddress((void**)&wt,  g_wt);
    cudaGetSymbolAddress((void**)&hpart, g_hpart);
    cudaGetSymbolAddress((void**)&kpart, g_kpart);
    cudaGetSymbolAddress((void**)&bns, g_bns);
    cudaGetSymbolAddress((void**)&bnq, g_bnq);
    cudaGetSymbolAddress((void**)&ksum, g_ksum);
    cudaGetSymbolAddress((void**)&vsum, g_vsum);
    cudaGetSymbolAddress((void**)&scale, g_scale);
    cudaGetSymbolAddress((void**)&shift, g_shift);
    cudaGetSymbolAddress((void**)&den, g_den);
    cudaGetSymbolAddress((void**)&dis, g_dis);
    cudaGetSymbolAddress((void**)&aw,  g_aw);
    cudaGetSymbolAddress((void**)&deg, g_deg);
    cudaGetSymbolAddress((void**)&indptr, g_indptr);
    cudaGetSymbolAddress((void**)&cursor, g_cursor);
    cudaGetSymbolAddress((void**)&arow, g_arow);

    const float* wtWin = wt;
    const float* wtWq  = wt + 16384;
    const float* wtWk  = wt + 49152;
    const float* wtWfc = wt + 81920;

    cudaFuncSetAttribute(sgemm_mma<1,3,0>, cudaFuncAttributeMaxDynamicSharedMemorySize, SM_TOTAL);
    cudaFuncSetAttribute(sgemm_mma<1,5,1>, cudaFuncAttributeMaxDynamicSharedMemorySize, SM_TOTAL);
    cudaFuncSetAttribute(sgemm_mma<1,7,0>, cudaFuncAttributeMaxDynamicSharedMemorySize, SM_TOTAL);
    cudaFuncSetAttribute(sgemm_mma<5,8,0>, cudaFuncAttributeMaxDynamicSharedMemorySize, SM_TOTAL);
    cudaFuncSetAttribute(kvs_mma, cudaFuncAttributeMaxDynamicSharedMemorySize, KV_SMEM);

    const int WARP_GRID = (NN + 7)/8;

    static cudaStream_t s1 = nullptr, s2 = nullptr;
    static cudaEvent_t e0, e1, eF[2], eK[2], eS1[2], eQ[2];
    if(s1 == nullptr){
        cudaStreamCreateWithFlags(&s1, cudaStreamNonBlocking);
        cudaStreamCreateWithFlags(&s2, cudaStreamNonBlocking);
        cudaEventCreateWithFlags(&e0, cudaEventDisableTiming);
        cudaEventCreateWithFlags(&e1, cudaEventDisableTiming);
        for(int i=0;i<2;i++){
            cudaEventCreateWithFlags(&eF[i],  cudaEventDisableTiming);
            cudaEventCreateWithFlags(&eK[i],  cudaEventDisableTiming);
            cudaEventCreateWithFlags(&eS1[i], cudaEventDisableTiming);
            cudaEventCreateWithFlags(&eQ[i],  cudaEventDisableTiming);
        }
    }

    // ---- fork: graph preprocessing on s1; weight cvt + input layer on stream 0 ----
    cudaEventRecord(e0, 0);
    cudaStreamWaitEvent(s1, e0, 0);
    cudaMemsetAsync(deg, 0, NN*sizeof(int), s1);
    deg_count<<<(EE+255)/256, 256, 0, s1>>>(col, deg);
    dis_kernel<<<(NN+255)/256, 256, 0, s1>>>(deg, dis);
    scan_kernel<<<1, 1024, 0, s1>>>(deg, indptr, cursor);
    csr_fill<<<(EE+255)/256, 256, 0, s1>>>(row, col, dis, cursor, arow, aw);
    cudaEventRecord(e1, s1);

    cvt_weights<<<(15*16384+255)/256, 256>>>(W_in, Wq, Wk, Wfc, wt);
    {
        Parts P; P.p[0]=x; P.p[1]=0; P.p[2]=0; P.p[3]=0; P.p[4]=0;
        PartsB B; B.p[0]=wtWin; B.p[1]=0; B.p[2]=0; B.p[3]=0; B.p[4]=0;
        sgemm_mma<1,5,1><<<TCG,256,SM_TOTAL>>>(P, B, b_in, nullptr, nullptr, nullptr,
                                               z, bns, bnq, NN);
        bn_finish<<<1,1024>>>(bns, bnq, bn_g + 0*HD, bn_b + 0*HD, scale, shift, TCG);
        bn_apply_relu<<<BAP,HD>>>(z, scale, shift, h, hpart);
    }

    for(int i=0;i<2;i++){
        Parts Ph; Ph.p[0]=h; Ph.p[1]=0; Ph.p[2]=0; Ph.p[3]=0; Ph.p[4]=0;
        const float* Wfci = Wfc + (size_t)i*640*HD;           // original (for kvs_w0)
        const float* wtWfci = wtWfc + (size_t)i*640*HD;       // pre-rounded

        cudaEventRecord(eF[i], 0);
        cudaStreamWaitEvent(s1, eF[i], 0);
        cudaStreamWaitEvent(s2, eF[i], 0);

        // ---- s1: vsum, k-GEMM -> ksum -> kvs -> W0p/c0 ----
        colsum_reduce<<<1,1024,0,s1>>>(hpart, vsum, BAP);
        {
            PartsB Bk; Bk.p[0]=wtWk + (size_t)i*HD*HD; Bk.p[1]=0; Bk.p[2]=0; Bk.p[3]=0; Bk.p[4]=0;
            sgemm_mma<1,3,0><<<TCG,256,SM_TOTAL,s1>>>(Ph, Bk, bk + i*HD, nullptr, nullptr,
                                                      nullptr, k, kpart, nullptr, NN);
        }
        colsum_reduce<<<1,1024,0,s1>>>(kpart, ksum, TCG);
        cudaEventRecord(eK[i], s1);
        kvs_mma<<<KVB2,256,KV_SMEM,s1>>>(k, h, kvspart);
        kvs_reduce<<<(HD*HD+255)/256,256,0,s1>>>(kvspart, kvs);
        kvs_w0<<<HD+1,HD,0,s1>>>(kvs, vsum, Wfci, w0p, c0);
        cudaEventRecord(eS1[i], s1);

        // ---- s2: q-GEMM (norm only) -> den + row scale (rounded) ----
        {
            PartsB Bq; Bq.p[0]=wtWq + (size_t)i*HD*HD; Bq.p[1]=0; Bq.p[2]=0; Bq.p[3]=0; Bq.p[4]=0;
            sgemm_mma<1,7,0><<<TCG,256,SM_TOTAL,s2>>>(Ph, Bq, bq + i*HD, nullptr, nullptr,
                                                      nullptr, q, nullptr, nullptr, NN);
        }
        cudaStreamWaitEvent(s2, eK[i], 0);
        den_scale<<<WARP_GRID,256,0,s2>>>(q, ksum, den);
        cudaEventRecord(eQ[i], s2);

        // ---- s0: prop chain ----
        if(i == 0) cudaStreamWaitEvent(0, e1, 0);
        prop_kernel<<<WARP_GRID,256>>>(indptr, arow, aw, h,  p1);
        prop_kernel<<<WARP_GRID,256>>>(indptr, arow, aw, p1, p2);
        prop_kernel<<<WARP_GRID,256>>>(indptr, arow, aw, p2, p3);

        // ---- join: Wfc 5-part with W0p substitution (+BN partials) ----
        cudaStreamWaitEvent(0, eS1[i], 0);
        cudaStreamWaitEvent(0, eQ[i], 0);
        {
            Parts P5; P5.p[0]=q; P5.p[1]=h; P5.p[2]=p1; P5.p[3]=p2; P5.p[4]=p3;
            PartsB B5; B5.p[0]=w0p;
            B5.p[1]=wtWfci + 1*HD*HD; B5.p[2]=wtWfci + 2*HD*HD;
            B5.p[3]=wtWfci + 3*HD*HD; B5.p[4]=wtWfci + 4*HD*HD;
            sgemm_mma<5,8,0><<<TCG,256,SM_TOTAL>>>(P5, B5, bfc + i*HD, c0, den, h,
                                                   z, bns, bnq, NN);
        }
        bn_finish<<<1,1024>>>(bns, bnq, bn_g + (i+1)*HD, bn_b + (i+1)*HD, scale, shift, TCG);
        bn_apply_relu<<<BAP,HD>>>(z, scale, shift, h, hpart);
    }

    out_gemm<<<WARP_GRID,256>>>(h, W_out, b_out, out);
}

// round 16
// speedup vs baseline: 1.5241x; 1.0276x over previous
#include <cuda_runtime.h>
#include <cuda_fp16.h>
#include <cstdint>
#include <math.h>

#define NN 50000
#define EE 800000
#define HD 128
#define KVB2 196
#define BAP 512
#define TCG 391
#define EPSI 1e-5f

__device__ __forceinline__ uint32_t f2tf32(float f){
    uint32_t r; asm("cvt.rna.tf32.f32 %0, %1;" : "=r"(r) : "f"(f)); return r;
}
__device__ __forceinline__ float rtf(float v){ return __uint_as_float(f2tf32(v)); }
__device__ __forceinline__ uint32_t smem_u32(const void* p){
    uint32_t a;
    asm("{ .reg .u64 t; cvta.to.shared.u64 t, %1; cvt.u32.u64 %0, t; }" : "=r"(a) : "l"(p));
    return a;
}
__device__ __forceinline__ void cp16(uint32_t dst, const float* src, bool pred){
    asm volatile("cp.async.cg.shared.global [%0], [%1], 16, %2;"
        :: "r"(dst), "l"(src), "r"(pred ? 16 : 0));
}
#define CP_COMMIT() asm volatile("cp.async.commit_group;" ::: "memory")
#define CP_WAIT1()  asm volatile("cp.async.wait_group 1;" ::: "memory")
#define CP_WAIT0()  asm volatile("cp.async.wait_group 0;" ::: "memory")

// ================= scratch =================
__device__ float g_h [NN*HD];
__device__ float g_z [NN*HD];
__device__ float g_q [NN*HD];
__device__ float g_k [NN*HD];
__device__ float g_p1[NN*HD];
__device__ float g_p2[NN*HD];
__device__ float g_p3[NN*HD];
__device__ __half g_h16 [NN*HD];
__device__ __half g_t16a[NN*HD];
__device__ __half g_t16b[NN*HD];
__device__ float g_kvspart[KVB2*HD*HD];
__device__ float g_kvs[HD*HD];
__device__ float g_w0p[HD*HD];
__device__ float g_c0[HD];
__device__ float g_wt[15*16384];     // tf32-prerounded weights
__device__ float g_hpart[BAP*HD];
__device__ float g_kpart[TCG*HD];
__device__ float g_bns[TCG*HD];
__device__ float g_bnq[TCG*HD];
__device__ float g_ksum[HD];
__device__ float g_vsum[HD];
__device__ float g_scale[HD];
__device__ float g_shift[HD];
__device__ float g_den[NN];
__device__ int   g_deg[NN];
__device__ float g_dis[NN];
__device__ int   g_indptr[NN+1];
__device__ int   g_cursor[NN];
__device__ int   g_arow[EE];
__device__ float g_aw[EE];

// ================= weight conversion (once per launch) =================
__global__ void cvt_weights(const float* __restrict__ Win, const float* __restrict__ Wq,
                            const float* __restrict__ Wk, const float* __restrict__ Wfc,
                            float* __restrict__ wt){
    int i = blockIdx.x*256 + threadIdx.x;      // 245760 total
    if(i >= 15*16384) return;
    float v;
    if(i < 16384)       v = Win[i];
    else if(i < 49152)  v = Wq[i - 16384];
    else if(i < 81920)  v = Wk[i - 49152];
    else                v = Wfc[i - 81920];
    wt[i] = rtf(v);
}

// ================= graph preprocessing =================
__global__ void deg_count(const int* __restrict__ col, int* __restrict__ deg){
    int e = blockIdx.x*blockDim.x + threadIdx.x;
    if(e < EE) atomicAdd(&deg[col[e]], 1);
}
__global__ void dis_kernel(const int* __restrict__ deg, float* __restrict__ dis){
    int i = blockIdx.x*blockDim.x + threadIdx.x;
    if(i < NN) dis[i] = deg[i] > 0 ? rsqrtf((float)deg[i]) : 0.0f;
}
__global__ void scan_kernel(const int* __restrict__ deg, int* __restrict__ indptr,
                            int* __restrict__ cursor){
    __shared__ int sh[1024];
    __shared__ int carry;
    int tid = threadIdx.x;
    if(tid == 0) carry = 0;
    __syncthreads();
    for(int base = 0; base < NN; base += 1024){
        int i = base + tid;
        int v = (i < NN) ? deg[i] : 0;
        sh[tid] = v; __syncthreads();
        for(int off = 1; off < 1024; off <<= 1){
            int t = (tid >= off) ? sh[tid-off] : 0;
            __syncthreads();
            sh[tid] += t;
            __syncthreads();
        }
        int incl = sh[tid];
        int c0 = carry;
        if(i < NN){ indptr[i] = c0 + incl - v; cursor[i] = c0 + incl - v; }
        __syncthreads();
        if(tid == 1023) carry = c0 + incl;
        __syncthreads();
    }
    if(tid == 1023) indptr[NN] = carry;
}
__global__ void csr_fill(const int* __restrict__ row, const int* __restrict__ col,
                         const float* __restrict__ dis, int* __restrict__ cursor,
                         int* __restrict__ arow, float* __restrict__ aw){
    int e = blockIdx.x*blockDim.x + threadIdx.x;
    if(e >= EE) return;
    int c = col[e], r = row[e];
    int p = atomicAdd(&cursor[c], 1);
    arow[p] = r;
    aw[p]   = dis[c] * dis[r];
}

// prop (fp16 gather): out[c,:] = round_fp16( sum_j w_j * in16[r_j,:] )
// fp16 round == tf32 round for these magnitudes (both 10-bit mantissa).
__global__ void prop16(const int* __restrict__ indptr, const int* __restrict__ arow,
                       const float* __restrict__ aw, const __half* __restrict__ in,
                       float* __restrict__ out, __half* __restrict__ out16){
    int n = blockIdx.x*8 + (threadIdx.x >> 5);
    if(n >= NN) return;
    int lane = threadIdx.x & 31;
    float4 acc = make_float4(0.f,0.f,0.f,0.f);
    int s = indptr[n], e = indptr[n+1];
    int j = s;
    for(; j + 1 < e; j += 2){
        int r0 = arow[j], r1 = arow[j+1];
        float w0 = aw[j], w1 = aw[j+1];
        uint2 u0 = *(const uint2*)(in + (size_t)r0*HD + lane*4);
        uint2 u1 = *(const uint2*)(in + (size_t)r1*HD + lane*4);
        float2 a0 = __half22float2(*(__half2*)&u0.x);
        float2 a1 = __half22float2(*(__half2*)&u0.y);
        float2 b0 = __half22float2(*(__half2*)&u1.x);
        float2 b1 = __half22float2(*(__half2*)&u1.y);
        acc.x += w0*a0.x + w1*b0.x; acc.y += w0*a0.y + w1*b0.y;
        acc.z += w0*a1.x + w1*b1.x; acc.w += w0*a1.y + w1*b1.y;
    }
    if(j < e){
        int r = arow[j]; float w = aw[j];
        uint2 u = *(const uint2*)(in + (size_t)r*HD + lane*4);
        float2 a0 = __half22float2(*(__half2*)&u.x);
        float2 a1 = __half22float2(*(__half2*)&u.y);
        acc.x += w*a0.x; acc.y += w*a0.y; acc.z += w*a1.x; acc.w += w*a1.y;
    }
    __half2 o0 = __floats2half2_rn(acc.x, acc.y);
    __half2 o1 = __floats2half2_rn(acc.z, acc.w);
    float2 g0 = __half22float2(o0), g1 = __half22float2(o1);
    ((float4*)(out + (size_t)n*HD))[lane] = make_float4(g0.x, g0.y, g1.x, g1.y);
    if(out16){
        uint2 uo; uo.x = *(uint32_t*)&o0; uo.y = *(uint32_t*)&o1;
        *(uint2*)(out16 + (size_t)n*HD + lane*4) = uo;
    }
}

// den[n] = dot(qn[n,:], ksum) + NN;  q[n,:] = round_tf32(q[n,:]/den[n])
__global__ void den_scale(float* __restrict__ q, const float* __restrict__ ksum,
                          float* __restrict__ den){
    int n = blockIdx.x*8 + (threadIdx.x >> 5);
    if(n >= NN) return;
    int lane = threadIdx.x & 31;
    float4* p = (float4*)(q + (size_t)n*HD);
    float4 v = p[lane];
    float4 k4 = ((const float4*)ksum)[lane];
    float d = v.x*k4.x + v.y*k4.y + v.z*k4.z + v.w*k4.w;
    #pragma unroll
    for(int o=16;o;o>>=1) d += __shfl_xor_sync(0xffffffffu, d, o);
    d += (float)NN;
    if(lane == 0) den[n] = d;
    float inv = 1.f/d;
    v.x = rtf(v.x*inv); v.y = rtf(v.y*inv); v.z = rtf(v.z*inv); v.w = rtf(v.w*inv);
    p[lane] = v;
}

// W0p = round_tf32(kvs @ W0), c0 = vsum @ W0 (fp32). Grid = 129.
__global__ void kvs_w0(const float* __restrict__ kvs, const float* __restrict__ vsum,
                       const float* __restrict__ W0,
                       float* __restrict__ W0p, float* __restrict__ c0){
    int m = blockIdx.x;
    int j = threadIdx.x;
    const float* rowp = (m < HD) ? (kvs + (size_t)m*HD) : vsum;
    float s = 0.f;
    #pragma unroll 4
    for(int d = 0; d < HD; d++) s += rowp[d] * __ldg(W0 + (size_t)d*HD + j);
    if(m < HD) W0p[(size_t)m*HD + j] = rtf(s);
    else       c0[j] = s;
}

// ================= tf32 mma.sync GEMM, pre-rounded operands ====
// MODE 3: C = round(rownorm(acc + v1)); cs[blk] = col partials
// MODE 5: C = acc + v1;          cs/cq[blk] = col sum / sumsq
// MODE 7: C = rownorm(acc + v1)  (norm only)
// MODE 8: C = acc + v1 + res + v2[col]/den[row]; cs/cq[blk]
struct Parts  { const float* p[5]; };
struct PartsB { const float* p[5]; };

#define SA0 0
#define SA1 18432
#define SB0 36864
#define SB1 54272
#define SM_TOTAL 71680

template<int NPARTS, int MODE, int CVTA>
__global__ __launch_bounds__(256, 2)
void sgemm_mma(Parts parts, PartsB bparts,
               const float* __restrict__ v1, const float* __restrict__ v2,
               float* den, const float* __restrict__ res,
               float* __restrict__ C, float* __restrict__ cs, float* __restrict__ cq,
               int M){
    extern __shared__ char smem[];
    uint32_t sb = smem_u32(smem);
    int tid = threadIdx.x;
    int w = tid >> 5, lane = tid & 31;
    int g = lane >> 2, t = lane & 3;
    int m0 = (w & 3) * 32;
    int n0 = (w >> 2) * 64;
    int bm = blockIdx.x * 128;
    const int NCH = 4*NPARTS;

    float acc[2][8][4];
    #pragma unroll
    for(int mt=0;mt<2;mt++)
        #pragma unroll
        for(int nt=0;nt<8;nt++)
            #pragma unroll
            for(int i=0;i<4;i++) acc[mt][nt][i] = 0.f;

    auto prefetch = [&](int ch, int st){
        const float* A  = parts.p[ch>>2];
        const float* Bp = bparts.p[ch>>2];
        int kcc = ch & 3;
        uint32_t da = sb + (st ? SA1 : SA0);
        uint32_t db = sb + (st ? SB1 : SB0);
        #pragma unroll
        for(int it=0; it<4; ++it){
            int idx = tid + it*256;
            int r = idx >> 3, c4 = idx & 7;
            int gr = bm + r;
            int grc = (gr < M) ? gr : (M-1);
            cp16(da + (uint32_t)(r*36 + c4*4)*4,
                 A + (size_t)grc*HD + kcc*32 + c4*4, gr < M);
        }
        #pragma unroll
        for(int it=0; it<4; ++it){
            int idx = tid + it*256;
            int r = idx >> 5, c4 = idx & 31;
            cp16(db + (uint32_t)(r*136 + c4*4)*4,
                 Bp + (size_t)(kcc*32 + r)*HD + c4*4, true);
        }
    };

    prefetch(0, 0); CP_COMMIT();
    #pragma unroll 1
    for(int ch=0; ch<NCH; ++ch){
        int st = ch & 1;
        if(ch+1 < NCH){ prefetch(ch+1, st^1); CP_COMMIT(); CP_WAIT1(); }
        else CP_WAIT0();
        __syncthreads();
        const uint32_t* cA = (const uint32_t*)(smem + (st ? SA1 : SA0));
        const uint32_t* cB = (const uint32_t*)(smem + (st ? SB1 : SB0));
        #pragma unroll
        for(int ks=0; ks<4; ++ks){
            int k0 = ks*8;
            uint32_t a[2][4], b[8][2];
            #pragma unroll
            for(int mt=0;mt<2;mt++){
                int rb = m0 + mt*16 + g;
                a[mt][0] = cA[rb*36 + k0 + t];
                a[mt][1] = cA[(rb+8)*36 + k0 + t];
                a[mt][2] = cA[rb*36 + k0 + t + 4];
                a[mt][3] = cA[(rb+8)*36 + k0 + t + 4];
            }
            #pragma unroll
            for(int nt=0;nt<8;nt++){
                int nc = n0 + nt*8 + g;
                b[nt][0] = cB[(k0+t)*136 + nc];
                b[nt][1] = cB[(k0+t+4)*136 + nc];
            }
            if(CVTA){
                #pragma unroll
                for(int mt=0;mt<2;mt++)
                    #pragma unroll
                    for(int i=0;i<4;i++) a[mt][i] = f2tf32(__uint_as_float(a[mt][i]));
            }
            #pragma unroll
            for(int mt=0;mt<2;mt++){
                #pragma unroll
                for(int nt=0;nt<8;nt++){
                    asm volatile(
                        "mma.sync.aligned.m16n8k8.row.col.f32.tf32.tf32.f32 "
                        "{%0,%1,%2,%3}, {%4,%5,%6,%7}, {%8,%9}, {%0,%1,%2,%3};"
                        : "+f"(acc[mt][nt][0]), "+f"(acc[mt][nt][1]),
                          "+f"(acc[mt][nt][2]), "+f"(acc[mt][nt][3])
                        : "r"(a[mt][0]), "r"(a[mt][1]), "r"(a[mt][2]), "r"(a[mt][3]),
                          "r"(b[nt][0]), "r"(b[nt][1]));
                }
            }
        }
        __syncthreads();
    }

    // ---------- epilogue ----------
    float* sred  = (float*)smem;
    float* scol  = (float*)(smem + 2048);
    float* sqol  = (float*)(smem + 4096);

    float be[8][2];
    #pragma unroll
    for(int nt=0;nt<8;nt++){
        int c0i = n0 + nt*8 + 2*t;
        be[nt][0] = __ldg(v1 + c0i); be[nt][1] = __ldg(v1 + c0i + 1);
    }

    if(MODE == 3 || MODE == 7){
        float ss[2][2] = {{0.f,0.f},{0.f,0.f}};
        #pragma unroll
        for(int mt=0;mt<2;mt++){
            #pragma unroll
            for(int nt=0;nt<8;nt++){
                float o0 = acc[mt][nt][0] + be[nt][0];
                float o1 = acc[mt][nt][1] + be[nt][1];
                float o2 = acc[mt][nt][2] + be[nt][0];
                float o3 = acc[mt][nt][3] + be[nt][1];
                acc[mt][nt][0]=o0; acc[mt][nt][1]=o1; acc[mt][nt][2]=o2; acc[mt][nt][3]=o3;
                ss[mt][0] += o0*o0 + o1*o1;
                ss[mt][1] += o2*o2 + o3*o3;
            }
        }
        #pragma unroll
        for(int off=1; off<=2; off<<=1){
            #pragma unroll
            for(int mt=0;mt<2;mt++){
                ss[mt][0] += __shfl_xor_sync(0xffffffffu, ss[mt][0], off);
                ss[mt][1] += __shfl_xor_sync(0xffffffffu, ss[mt][1], off);
            }
        }
        int half = w >> 2;
        if(t == 0){
            #pragma unroll
            for(int mt=0;mt<2;mt++){
                sred[half*128 + m0 + mt*16 + g]     = ss[mt][0];
                sred[half*128 + m0 + mt*16 + g + 8] = ss[mt][1];
            }
        }
        __syncthreads();
        float inv[2][2];
        #pragma unroll
        for(int mt=0;mt<2;mt++){
            #pragma unroll
            for(int j=0;j<2;j++){
                int rl = m0 + mt*16 + g + j*8;
                inv[mt][j] = rsqrtf(sred[rl] + sred[128 + rl]);
            }
        }
        float ca[8][2];
        #pragma unroll
        for(int nt=0;nt<8;nt++){ ca[nt][0]=0.f; ca[nt][1]=0.f; }
        #pragma unroll
        for(int mt=0;mt<2;mt++){
            int r1 = bm + m0 + mt*16 + g, r2 = r1 + 8;
            bool ok1 = r1 < M, ok2 = r2 < M;
            #pragma unroll
            for(int nt=0;nt<8;nt++){
                int cc = n0 + nt*8 + 2*t;
                float o0 = acc[mt][nt][0]*inv[mt][0];
                float o1 = acc[mt][nt][1]*inv[mt][0];
                float o2 = acc[mt][nt][2]*inv[mt][1];
                float o3 = acc[mt][nt][3]*inv[mt][1];
                if(MODE == 3){   // k feeds kvs_mma: store pre-rounded
                    o0 = rtf(o0); o1 = rtf(o1); o2 = rtf(o2); o3 = rtf(o3);
                }
                if(ok1) *(float2*)(C + (size_t)r1*HD + cc) = make_float2(o0, o1);
                if(ok2) *(float2*)(C + (size_t)r2*HD + cc) = make_float2(o2, o3);
                if(MODE == 3){
                    ca[nt][0] += (ok1?o0:0.f) + (ok2?o2:0.f);
                    ca[nt][1] += (ok1?o1:0.f) + (ok2?o3:0.f);
                }
            }
        }
        if(MODE == 3){
            #pragma unroll
            for(int off=4; off<=16; off<<=1)
                #pragma unroll
                for(int nt=0;nt<8;nt++){
                    ca[nt][0] += __shfl_xor_sync(0xffffffffu, ca[nt][0], off);
                    ca[nt][1] += __shfl_xor_sync(0xffffffffu, ca[nt][1], off);
                }
            if(lane < 4){
                #pragma unroll
                for(int nt=0;nt<8;nt++){
                    scol[w*64 + nt*8 + 2*t]     = ca[nt][0];
                    scol[w*64 + nt*8 + 2*t + 1] = ca[nt][1];
                }
            }
            __syncthreads();
            if(tid < 128){
                int c = tid, hf = c >> 6, cl = c & 63;
                float s = 0.f;
                #pragma unroll
                for(int j=0;j<4;j++) s += scol[(hf*4+j)*64 + cl];
                cs[blockIdx.x*HD + c] = s;
            }
        }
    } else { // MODE 5 / 8
        float ce[8][2];
        if(MODE == 8){
            #pragma unroll
            for(int nt=0;nt<8;nt++){
                int c0i = n0 + nt*8 + 2*t;
                ce[nt][0] = __ldg(v2 + c0i); ce[nt][1] = __ldg(v2 + c0i + 1);
            }
        }
        float ca[8][2], cqv[8][2];
        #pragma unroll
        for(int nt=0;nt<8;nt++){ ca[nt][0]=0.f; ca[nt][1]=0.f; cqv[nt][0]=0.f; cqv[nt][1]=0.f; }
        #pragma unroll
        for(int mt=0;mt<2;mt++){
            int r1 = bm + m0 + mt*16 + g, r2 = r1 + 8;
            bool ok1 = r1 < M, ok2 = r2 < M;
            float i1 = 0.f, i2 = 0.f;
            if(MODE == 8){
                if(ok1) i1 = 1.f/den[r1];
                if(ok2) i2 = 1.f/den[r2];
            }
            #pragma unroll
            for(int nt=0;nt<8;nt++){
                int cc = n0 + nt*8 + 2*t;
                float o0 = acc[mt][nt][0] + be[nt][0];
                float o1 = acc[mt][nt][1] + be[nt][1];
                float o2 = acc[mt][nt][2] + be[nt][0];
                float o3 = acc[mt][nt][3] + be[nt][1];
                if(MODE == 8){
                    o0 += ce[nt][0]*i1; o1 += ce[nt][1]*i1;
                    o2 += ce[nt][0]*i2; o3 += ce[nt][1]*i2;
                    if(ok1){
                        float2 rv = *(const float2*)(res + (size_t)r1*HD + cc);
                        o0 += rv.x; o1 += rv.y;
                    }
                    if(ok2){
                        float2 rv = *(const float2*)(res + (size_t)r2*HD + cc);
                        o2 += rv.x; o3 += rv.y;
                    }
                }
                if(ok1) *(float2*)(C + (size_t)r1*HD + cc) = make_float2(o0, o1);
                if(ok2) *(float2*)(C + (size_t)r2*HD + cc) = make_float2(o2, o3);
                ca[nt][0]  += (ok1?o0:0.f) + (ok2?o2:0.f);
                ca[nt][1]  += (ok1?o1:0.f) + (ok2?o3:0.f);
                cqv[nt][0] += (ok1?o0*o0:0.f) + (ok2?o2*o2:0.f);
                cqv[nt][1] += (ok1?o1*o1:0.f) + (ok2?o3*o3:0.f);
            }
        }
        #pragma unroll
        for(int off=4; off<=16; off<<=1)
            #pragma unroll
            for(int nt=0;nt<8;nt++){
                ca[nt][0]  += __shfl_xor_sync(0xffffffffu, ca[nt][0], off);
                ca[nt][1]  += __shfl_xor_sync(0xffffffffu, ca[nt][1], off);
                cqv[nt][0] += __shfl_xor_sync(0xffffffffu, cqv[nt][0], off);
                cqv[nt][1] += __shfl_xor_sync(0xffffffffu, cqv[nt][1], off);
            }
        if(lane < 4){
            #pragma unroll
            for(int nt=0;nt<8;nt++){
                scol[w*64 + nt*8 + 2*t]     = ca[nt][0];
                scol[w*64 + nt*8 + 2*t + 1] = ca[nt][1];
                sqol[w*64 + nt*8 + 2*t]     = cqv[nt][0];
                sqol[w*64 + nt*8 + 2*t + 1] = cqv[nt][1];
            }
        }
        __syncthreads();
        if(tid < 128){
            int c = tid, hf = c >> 6, cl = c & 63;
            float s = 0.f, qq = 0.f;
            #pragma unroll
            for(int j=0;j<4;j++){ s += scol[(hf*4+j)*64 + cl]; qq += sqol[(hf*4+j)*64 + cl]; }
            cs[blockIdx.x*HD + c] = s;
            cq[blockIdx.x*HD + c] = qq;
        }
    }
}

// ================= kvs via tensor cores (inputs pre-rounded) =================
#define KV_SA 0
#define KV_SB 34816
#define KV_SMEM 69632

__global__ __launch_bounds__(256, 2)
void kvs_mma(const float* __restrict__ kn, const float* __restrict__ vv,
             float* __restrict__ part){
    extern __shared__ char smem[];
    float* sA = (float*)(smem + KV_SA);
    float* sB = (float*)(smem + KV_SB);
    int tid = threadIdx.x;
    int w = tid >> 5, lane = tid & 31;
    int g = lane >> 2, t = lane & 3;
    int m0 = (w & 3) * 32;
    int n0 = (w >> 2) * 64;
    int base = blockIdx.x * 256;

    float acc[2][8][4];
    #pragma unroll
    for(int mt=0;mt<2;mt++)
        #pragma unroll
        for(int nt=0;nt<8;nt++)
            #pragma unroll
            for(int i=0;i<4;i++) acc[mt][nt][i] = 0.f;

    #pragma unroll 1
    for(int sub=0; sub<4; ++sub){
        int nb = base + sub*64;
        #pragma unroll
        for(int it=0; it<8; ++it){
            int idx = tid + it*256;
            int r = idx >> 5, c4 = idx & 31;
            int gn = nb + r;
            bool ok = gn < NN;
            float4 ka = ok ? ((const float4*)(kn + (size_t)gn*HD))[c4] : make_float4(0,0,0,0);
            float4 va = ok ? ((const float4*)(vv + (size_t)gn*HD))[c4] : make_float4(0,0,0,0);
            *(float4*)(sA + r*136 + c4*4) = ka;
            *(float4*)(sB + r*136 + c4*4) = va;
        }
        __syncthreads();
        #pragma unroll
        for(int ks=0; ks<8; ++ks){
            int k0 = ks*8;
            uint32_t a[2][4], b[8][2];
            const uint32_t* uA = (const uint32_t*)sA;
            const uint32_t* uB = (const uint32_t*)sB;
            #pragma unroll
            for(int mt=0;mt<2;mt++){
                int rb = m0 + mt*16 + g;
                a[mt][0] = uA[(k0+t)*136 + rb];
                a[mt][1] = uA[(k0+t)*136 + rb + 8];
                a[mt][2] = uA[(k0+t+4)*136 + rb];
                a[mt][3] = uA[(k0+t+4)*136 + rb + 8];
            }
            #pragma unroll
            for(int nt=0;nt<8;nt++){
                int nc = n0 + nt*8 + g;
                b[nt][0] = uB[(k0+t)*136 + nc];
                b[nt][1] = uB[(k0+t+4)*136 + nc];
            }
            #pragma unroll
            for(int mt=0;mt<2;mt++){
                #pragma unroll
                for(int nt=0;nt<8;nt++){
                    asm volatile(
                        "mma.sync.aligned.m16n8k8.row.col.f32.tf32.tf32.f32 "
                        "{%0,%1,%2,%3}, {%4,%5,%6,%7}, {%8,%9}, {%0,%1,%2,%3};"
                        : "+f"(acc[mt][nt][0]), "+f"(acc[mt][nt][1]),
                          "+f"(acc[mt][nt][2]), "+f"(acc[mt][nt][3])
                        : "r"(a[mt][0]), "r"(a[mt][1]), "r"(a[mt][2]), "r"(a[mt][3]),
                          "r"(b[nt][0]), "r"(b[nt][1]));
                }
            }
        }
        __syncthreads();
    }

    float* P = part + (size_t)blockIdx.x*HD*HD;
    #pragma unroll
    for(int mt=0;mt<2;mt++){
        int r1 = m0 + mt*16 + g;
        int r2 = r1 + 8;
        #pragma unroll
        for(int nt=0;nt<8;nt++){
            int cc = n0 + nt*8 + 2*t;
            *(float2*)(P + (size_t)r1*HD + cc) = make_float2(acc[mt][nt][0], acc[mt][nt][1]);
            *(float2*)(P + (size_t)r2*HD + cc) = make_float2(acc[mt][nt][2], acc[mt][nt][3]);
        }
    }
}

__global__ void kvs_reduce(const float* __restrict__ part, float* __restrict__ kvs){
    int i = blockIdx.x*blockDim.x + threadIdx.x;
    if(i >= HD*HD) return;
    float s = 0.f;
    for(int b=0;b<KVB2;b++) s += part[(size_t)b*HD*HD + i];
    kvs[i] = s;
}

// ================= parallel small reductions =================
__global__ void colsum_reduce(const float* __restrict__ part, float* __restrict__ out,
                              int count){
    __shared__ float sh[8][128];
    int c = threadIdx.x & 127, sl = threadIdx.x >> 7;
    float s = 0.f;
    for(int b = sl; b < count; b += 8) s += part[b*HD + c];
    sh[sl][c] = s;
    __syncthreads();
    if(threadIdx.x < 128){
        float tot = 0.f;
        #pragma unroll
        for(int j=0;j<8;j++) tot += sh[j][c];
        out[c] = tot;
    }
}

__global__ void bn_finish(const float* __restrict__ ps, const float* __restrict__ pq,
                          const float* __restrict__ g, const float* __restrict__ b,
                          float* __restrict__ scale, float* __restrict__ shift,
                          int count){
    __shared__ float shs[8][128], shq[8][128];
    int c = threadIdx.x & 127, sl = threadIdx.x >> 7;
    float s = 0.f, q = 0.f;
    for(int i = sl; i < count; i += 8){ s += ps[i*HD+c]; q += pq[i*HD+c]; }
    shs[sl][c] = s; shq[sl][c] = q;
    __syncthreads();
    if(threadIdx.x < 128){
        float ts = 0.f, tq = 0.f;
        #pragma unroll
        for(int j=0;j<8;j++){ ts += shs[j][c]; tq += shq[j][c]; }
        float mean = ts / (float)NN;
        float var  = tq / (float)NN - mean*mean;
        float sc = g[c] * rsqrtf(var + EPSI);
        scale[c] = sc;
        shift[c] = b[c] - mean*sc;
    }
}

// BN apply + relu; writes fp32 h, fp16 h16, and column partial sums
__global__ void bn_apply_relu(const float* __restrict__ z, const float* __restrict__ scale,
                              const float* __restrict__ shift, float* __restrict__ h,
                              __half* __restrict__ h16, float* __restrict__ hpart){
    int c = threadIdx.x;
    int b = blockIdx.x;
    int chunk = (NN + BAP - 1)/BAP;
    int r0 = b*chunk, r1 = min(NN, r0 + chunk);
    float sc = scale[c], sh = shift[c];
    float s = 0.f;
    int r = r0;
    for(; r + 3 < r1; r += 4){
        float v0 = rtf(fmaxf(z[(size_t)(r+0)*HD + c]*sc + sh, 0.f));
        float v1 = rtf(fmaxf(z[(size_t)(r+1)*HD + c]*sc + sh, 0.f));
        float v2 = rtf(fmaxf(z[(size_t)(r+2)*HD + c]*sc + sh, 0.f));
        float v3 = rtf(fmaxf(z[(size_t)(r+3)*HD + c]*sc + sh, 0.f));
        h[(size_t)(r+0)*HD + c] = v0; h[(size_t)(r+1)*HD + c] = v1;
        h[(size_t)(r+2)*HD + c] = v2; h[(size_t)(r+3)*HD + c] = v3;
        h16[(size_t)(r+0)*HD + c] = __float2half_rn(v0);
        h16[(size_t)(r+1)*HD + c] = __float2half_rn(v1);
        h16[(size_t)(r+2)*HD + c] = __float2half_rn(v2);
        h16[(size_t)(r+3)*HD + c] = __float2half_rn(v3);
        s += v0 + v1 + v2 + v3;
    }
    for(; r < r1; ++r){
        float v = rtf(fmaxf(z[(size_t)r*HD + c]*sc + sh, 0.f));
        h[(size_t)r*HD + c] = v;
        h16[(size_t)r*HD + c] = __float2half_rn(v);
        s += v;
    }
    hpart[b*HD + c] = s;
}

__global__ void out_gemm(const float* __restrict__ h, const float* __restrict__ W,
                         const float* __restrict__ b, float* __restrict__ out){
    int n = blockIdx.x*8 + (threadIdx.x >> 5);
    if(n >= NN) return;
    int lane = threadIdx.x & 31;
    const float* hr = h + (size_t)n*HD;
    float acc0 = 0.f, acc1 = 0.f;
    #pragma unroll 8
    for(int k4=0;k4<32;k4++){
        float4 hv = ((const float4*)hr)[k4];
        int k = k4*4;
        acc0 += hv.x*__ldg(W + (k+0)*40 + lane);
        acc0 += hv.y*__ldg(W + (k+1)*40 + lane);
        acc0 += hv.z*__ldg(W + (k+2)*40 + lane);
        acc0 += hv.w*__ldg(W + (k+3)*40 + lane);
        if(lane < 8){
            acc1 += hv.x*__ldg(W + (k+0)*40 + 32 + lane);
            acc1 += hv.y*__ldg(W + (k+1)*40 + 32 + lane);
            acc1 += hv.z*__ldg(W + (k+2)*40 + 32 + lane);
            acc1 += hv.w*__ldg(W + (k+3)*40 + 32 + lane);
        }
    }
    out[(size_t)n*40 + lane] = acc0 + b[lane];
    if(lane < 8) out[(size_t)n*40 + 32 + lane] = acc1 + b[32 + lane];
}

// ================= host =================
extern "C" void kernel_launch(void* const* d_in, const int* in_sizes, int n_in,
                              void* d_out, int out_size){
    const float* x     = (const float*)d_in[0];
    const int*   ei    = (const int*)  d_in[1];
    const float* W_in  = (const float*)d_in[2];
    const float* b_in  = (const float*)d_in[3];
    const float* Wq    = (const float*)d_in[4];
    const float* bq    = (const float*)d_in[5];
    const float* Wk    = (const float*)d_in[6];
    const float* bk    = (const float*)d_in[7];
    const float* Wfc   = (const float*)d_in[8];
    const float* bfc   = (const float*)d_in[9];
    const float* W_out = (const float*)d_in[10];
    const float* b_out = (const float*)d_in[11];
    const float* bn_g  = (const float*)d_in[12];
    const float* bn_b  = (const float*)d_in[13];
    float* out = (float*)d_out;

    const int* row = ei;
    const int* col = ei + EE;

    float *h,*z,*q,*k,*p1,*p2,*p3,*kvspart,*kvs,*w0p,*c0,*wt,*hpart,*kpart,*bns,*bnq;
    float *ksum,*vsum,*scale,*shift,*den,*dis,*aw;
    __half *h16,*t16a,*t16b;
    int *deg,*indptr,*cursor,*arow;
    cudaGetSymbolAddress((void**)&h,  g_h);
    cudaGetSymbolAddress((void**)&z,  g_z);
    cudaGetSymbolAddress((void**)&q,  g_q);
    cudaGetSymbolAddress((void**)&k,  g_k);
    cudaGetSymbolAddress((void**)&p1, g_p1);
    cudaGetSymbolAddress((void**)&p2, g_p2);
    cudaGetSymbolAddress((void**)&p3, g_p3);
    cudaGetSymbolAddress((void**)&h16,  g_h16);
    cudaGetSymbolAddress((void**)&t16a, g_t16a);
    cudaGetSymbolAddress((void**)&t16b, g_t16b);
    cudaGetSymbolAddress((void**)&kvspart, g_kvspart);
    cudaGetSymbolAddress((void**)&kvs, g_kvs);
    cudaGetSymbolAddress((void**)&w0p, g_w0p);
    cudaGetSymbolAddress((void**)&c0,  g_c0);
    cudaGetSymbolAddress((void**)&wt,  g_wt);
    cudaGetSymbolAddress((void**)&hpart, g_hpart);
    cudaGetSymbolAddress((void**)&kpart, g_kpart);
    cudaGetSymbolAddress((void**)&bns, g_bns);
    cudaGetSymbolAddress((void**)&bnq, g_bnq);
    cudaGetSymbolAddress((void**)&ksum, g_ksum);
    cudaGetSymbolAddress((void**)&vsum, g_vsum);
    cudaGetSymbolAddress((void**)&scale, g_scale);
    cudaGetSymbolAddress((void**)&shift, g_shift);
    cudaGetSymbolAddress((void**)&den, g_den);
    cudaGetSymbolAddress((void**)&dis, g_dis);
    cudaGetSymbolAddress((void**)&aw,  g_aw);
    cudaGetSymbolAddress((void**)&deg, g_deg);
    cudaGetSymbolAddress((void**)&indptr, g_indptr);
    cudaGetSymbolAddress((void**)&cursor, g_cursor);
    cudaGetSymbolAddress((void**)&arow, g_arow);

    const float* wtWin = wt;
    const float* wtWq  = wt + 16384;
    const float* wtWk  = wt + 49152;
    const float* wtWfc = wt + 81920;

    cudaFuncSetAttribute(sgemm_mma<1,3,0>, cudaFuncAttributeMaxDynamicSharedMemorySize, SM_TOTAL);
    cudaFuncSetAttribute(sgemm_mma<1,5,1>, cudaFuncAttributeMaxDynamicSharedMemorySize, SM_TOTAL);
    cudaFuncSetAttribute(sgemm_mma<1,7,0>, cudaFuncAttributeMaxDynamicSharedMemorySize, SM_TOTAL);
    cudaFuncSetAttribute(sgemm_mma<5,8,0>, cudaFuncAttributeMaxDynamicSharedMemorySize, SM_TOTAL);
    cudaFuncSetAttribute(kvs_mma, cudaFuncAttributeMaxDynamicSharedMemorySize, KV_SMEM);

    const int WARP_GRID = (NN + 7)/8;

    static cudaStream_t s1 = nullptr, s2 = nullptr;
    static cudaEvent_t e0, e1, eF[2], eK[2], eS1[2], eQ[2];
    if(s1 == nullptr){
        cudaStreamCreateWithFlags(&s1, cudaStreamNonBlocking);
        cudaStreamCreateWithFlags(&s2, cudaStreamNonBlocking);
        cudaEventCreateWithFlags(&e0, cudaEventDisableTiming);
        cudaEventCreateWithFlags(&e1, cudaEventDisableTiming);
        for(int i=0;i<2;i++){
            cudaEventCreateWithFlags(&eF[i],  cudaEventDisableTiming);
            cudaEventCreateWithFlags(&eK[i],  cudaEventDisableTiming);
            cudaEventCreateWithFlags(&eS1[i], cudaEventDisableTiming);
            cudaEventCreateWithFlags(&eQ[i],  cudaEventDisableTiming);
        }
    }

    // ---- fork: graph preprocessing on s1; weight cvt + input layer on stream 0 ----
    cudaEventRecord(e0, 0);
    cudaStreamWaitEvent(s1, e0, 0);
    cudaMemsetAsync(deg, 0, NN*sizeof(int), s1);
    deg_count<<<(EE+255)/256, 256, 0, s1>>>(col, deg);
    dis_kernel<<<(NN+255)/256, 256, 0, s1>>>(deg, dis);
    scan_kernel<<<1, 1024, 0, s1>>>(deg, indptr, cursor);
    csr_fill<<<(EE+255)/256, 256, 0, s1>>>(row, col, dis, cursor, arow, aw);
    cudaEventRecord(e1, s1);

    cvt_weights<<<(15*16384+255)/256, 256>>>(W_in, Wq, Wk, Wfc, wt);
    {
        Parts P; P.p[0]=x; P.p[1]=0; P.p[2]=0; P.p[3]=0; P.p[4]=0;
        PartsB B; B.p[0]=wtWin; B.p[1]=0; B.p[2]=0; B.p[3]=0; B.p[4]=0;
        sgemm_mma<1,5,1><<<TCG,256,SM_TOTAL>>>(P, B, b_in, nullptr, nullptr, nullptr,
                                               z, bns, bnq, NN);
        bn_finish<<<1,1024>>>(bns, bnq, bn_g + 0*HD, bn_b + 0*HD, scale, shift, TCG);
        bn_apply_relu<<<BAP,HD>>>(z, scale, shift, h, h16, hpart);
    }

    for(int i=0;i<2;i++){
        Parts Ph; Ph.p[0]=h; Ph.p[1]=0; Ph.p[2]=0; Ph.p[3]=0; Ph.p[4]=0;
        const float* Wfci = Wfc + (size_t)i*640*HD;           // original (for kvs_w0)
        const float* wtWfci = wtWfc + (size_t)i*640*HD;       // pre-rounded

        cudaEventRecord(eF[i], 0);
        cudaStreamWaitEvent(s1, eF[i], 0);
        cudaStreamWaitEvent(s2, eF[i], 0);

        // ---- s1: vsum, k-GEMM -> ksum -> kvs -> W0p/c0 ----
        colsum_reduce<<<1,1024,0,s1>>>(hpart, vsum, BAP);
        {
            PartsB Bk; Bk.p[0]=wtWk + (size_t)i*HD*HD; Bk.p[1]=0; Bk.p[2]=0; Bk.p[3]=0; Bk.p[4]=0;
            sgemm_mma<1,3,0><<<TCG,256,SM_TOTAL,s1>>>(Ph, Bk, bk + i*HD, nullptr, nullptr,
                                                      nullptr, k, kpart, nullptr, NN);
        }
        colsum_reduce<<<1,1024,0,s1>>>(kpart, ksum, TCG);
        cudaEventRecord(eK[i], s1);
        kvs_mma<<<KVB2,256,KV_SMEM,s1>>>(k, h, kvspart);
        kvs_reduce<<<(HD*HD+255)/256,256,0,s1>>>(kvspart, kvs);
        kvs_w0<<<HD+1,HD,0,s1>>>(kvs, vsum, Wfci, w0p, c0);
        cudaEventRecord(eS1[i], s1);

        // ---- s2: q-GEMM (norm only) -> den + row scale (rounded) ----
        {
            PartsB Bq; Bq.p[0]=wtWq + (size_t)i*HD*HD; Bq.p[1]=0; Bq.p[2]=0; Bq.p[3]=0; Bq.p[4]=0;
            sgemm_mma<1,7,0><<<TCG,256,SM_TOTAL,s2>>>(Ph, Bq, bq + i*HD, nullptr, nullptr,
                                                      nullptr, q, nullptr, nullptr, NN);
        }
        cudaStreamWaitEvent(s2, eK[i], 0);
        den_scale<<<WARP_GRID,256,0,s2>>>(q, ksum, den);
        cudaEventRecord(eQ[i], s2);

        // ---- s0: prop chain (fp16 gathers) ----
        if(i == 0) cudaStreamWaitEvent(0, e1, 0);
        prop16<<<WARP_GRID,256>>>(indptr, arow, aw, h16,  p1, t16a);
        prop16<<<WARP_GRID,256>>>(indptr, arow, aw, t16a, p2, t16b);
        prop16<<<WARP_GRID,256>>>(indptr, arow, aw, t16b, p3, nullptr);

        // ---- join: Wfc 5-part with W0p substitution (+BN partials) ----
        cudaStreamWaitEvent(0, eS1[i], 0);
        cudaStreamWaitEvent(0, eQ[i], 0);
        {
            Parts P5; P5.p[0]=q; P5.p[1]=h; P5.p[2]=p1; P5.p[3]=p2; P5.p[4]=p3;
            PartsB B5; B5.p[0]=w0p;
            B5.p[1]=wtWfci + 1*HD*HD; B5.p[2]=wtWfci + 2*HD*HD;
            B5.p[3]=wtWfci + 3*HD*HD; B5.p[4]=wtWfci + 4*HD*HD;
            sgemm_mma<5,8,0><<<TCG,256,SM_TOTAL>>>(P5, B5, bfc + i*HD, c0, den, h,
                                                   z, bns, bnq, NN);
        }
        bn_finish<<<1,1024>>>(bns, bnq, bn_g + (i+1)*HD, bn_b + (i+1)*HD, scale, shift, TCG);
        bn_apply_relu<<<BAP,HD>>>(z, scale, shift, h, h16, hpart);
    }

    out_gemm<<<WARP_GRID,256>>>(h, W_out, b_out, out);
}

// round 17
// speedup vs baseline: 1.8122x; 1.1891x over previous
#include <cuda_runtime.h>
#include <cuda_fp16.h>
#include <cstdint>
#include <math.h>

#define NN 50000
#define EE 800000
#define HD 128
#define KVB2 196
#define BAP 512
#define TCG 391
#define EPSI 1e-5f

__device__ __forceinline__ uint32_t smem_u32(const void* p){
    uint32_t a;
    asm("{ .reg .u64 t; cvta.to.shared.u64 t, %1; cvt.u32.u64 %0, t; }" : "=r"(a) : "l"(p));
    return a;
}
__device__ __forceinline__ void cp16(uint32_t dst, const void* src, bool pred){
    asm volatile("cp.async.cg.shared.global [%0], [%1], 16, %2;"
        :: "r"(dst), "l"(src), "r"(pred ? 16 : 0));
}
#define CP_COMMIT() asm volatile("cp.async.commit_group;" ::: "memory")
#define CP_WAIT1()  asm volatile("cp.async.wait_group 1;" ::: "memory")
#define CP_WAIT0()  asm volatile("cp.async.wait_group 0;" ::: "memory")

// ================= scratch =================
__device__ float  g_z [NN*HD];
__device__ __half g_h16[NN*HD];
__device__ __half g_x16[NN*HD];
__device__ __half g_q16[NN*HD];
__device__ __half g_k16[NN*HD];
__device__ __half g_pa16[NN*HD];
__device__ __half g_pb16[NN*HD];
__device__ __half g_pc16[NN*HD];
__device__ float  g_kvspart[KVB2*HD*HD];
__device__ float  g_kvs[HD*HD];
__device__ __half g_w0p16[HD*HD];
__device__ float  g_c0[HD];
__device__ __half g_wt16[15*16384];    // fp16 weights, TRANSPOSED [n][k] per 128x128 part
__device__ float  g_hpart[BAP*HD];
__device__ float  g_kpart[TCG*HD];
__device__ float  g_bns[TCG*HD];
__device__ float  g_bnq[TCG*HD];
__device__ float  g_ksum[HD];
__device__ float  g_vsum[HD];
__device__ float  g_scale[HD];
__device__ float  g_shift[HD];
__device__ float  g_den[NN];           // holds den/NN
__device__ int    g_deg[NN];
__device__ float  g_dis[NN];
__device__ int    g_indptr[NN+1];
__device__ int    g_cursor[NN];
__device__ int    g_arow[EE];
__device__ float  g_aw[EE];

// ================= conversions (once per launch) =================
// weights -> fp16 transposed: wt16[part][n*128 + k] = W[part][k*128 + n]
__global__ void cvt_weights16(const float* __restrict__ Win, const float* __restrict__ Wq,
                              const float* __restrict__ Wk, const float* __restrict__ Wfc,
                              __half* __restrict__ wt){
    int i = blockIdx.x*256 + threadIdx.x;
    if(i >= 15*16384) return;
    int p = i >> 14, rem = i & 16383;
    int n = rem >> 7, kk = rem & 127;
    const float* base;
    int pl;
    if(p < 1){ base = Win; pl = p; }
    else if(p < 3){ base = Wq; pl = p - 1; }
    else if(p < 5){ base = Wk; pl = p - 3; }
    else { base = Wfc; pl = p - 5; }
    float v = base[(size_t)pl*16384 + kk*128 + n];
    wt[i] = __float2half_rn(v);
}

__global__ void cvt_x16(const float* __restrict__ x, __half* __restrict__ x16){
    int i = blockIdx.x*256 + threadIdx.x;
    if(i < NN*HD) x16[i] = __float2half_rn(x[i]);
}

// ================= graph preprocessing =================
__global__ void deg_count(const int* __restrict__ col, int* __restrict__ deg){
    int e = blockIdx.x*blockDim.x + threadIdx.x;
    if(e < EE) atomicAdd(&deg[col[e]], 1);
}
__global__ void dis_kernel(const int* __restrict__ deg, float* __restrict__ dis){
    int i = blockIdx.x*blockDim.x + threadIdx.x;
    if(i < NN) dis[i] = deg[i] > 0 ? rsqrtf((float)deg[i]) : 0.0f;
}
__global__ void scan_kernel(const int* __restrict__ deg, int* __restrict__ indptr,
                            int* __restrict__ cursor){
    __shared__ int sh[1024];
    __shared__ int carry;
    int tid = threadIdx.x;
    if(tid == 0) carry = 0;
    __syncthreads();
    for(int base = 0; base < NN; base += 1024){
        int i = base + tid;
        int v = (i < NN) ? deg[i] : 0;
        sh[tid] = v; __syncthreads();
        for(int off = 1; off < 1024; off <<= 1){
            int t = (tid >= off) ? sh[tid-off] : 0;
            __syncthreads();
            sh[tid] += t;
            __syncthreads();
        }
        int incl = sh[tid];
        int c0 = carry;
        if(i < NN){ indptr[i] = c0 + incl - v; cursor[i] = c0 + incl - v; }
        __syncthreads();
        if(tid == 1023) carry = c0 + incl;
        __syncthreads();
    }
    if(tid == 1023) indptr[NN] = carry;
}
__global__ void csr_fill(const int* __restrict__ row, const int* __restrict__ col,
                         const float* __restrict__ dis, int* __restrict__ cursor,
                         int* __restrict__ arow, float* __restrict__ aw){
    int e = blockIdx.x*blockDim.x + threadIdx.x;
    if(e >= EE) return;
    int c = col[e], r = row[e];
    int p = atomicAdd(&cursor[c], 1);
    arow[p] = r;
    aw[p]   = dis[c] * dis[r];
}

// prop (fp16 gather/store)
__global__ void prop16(const int* __restrict__ indptr, const int* __restrict__ arow,
                       const float* __restrict__ aw, const __half* __restrict__ in,
                       __half* __restrict__ out16){
    int n = blockIdx.x*8 + (threadIdx.x >> 5);
    if(n >= NN) return;
    int lane = threadIdx.x & 31;
    float4 acc = make_float4(0.f,0.f,0.f,0.f);
    int s = indptr[n], e = indptr[n+1];
    int j = s;
    for(; j + 1 < e; j += 2){
        int r0 = arow[j], r1 = arow[j+1];
        float w0 = aw[j], w1 = aw[j+1];
        uint2 u0 = *(const uint2*)(in + (size_t)r0*HD + lane*4);
        uint2 u1 = *(const uint2*)(in + (size_t)r1*HD + lane*4);
        float2 a0 = __half22float2(*(__half2*)&u0.x);
        float2 a1 = __half22float2(*(__half2*)&u0.y);
        float2 b0 = __half22float2(*(__half2*)&u1.x);
        float2 b1 = __half22float2(*(__half2*)&u1.y);
        acc.x += w0*a0.x + w1*b0.x; acc.y += w0*a0.y + w1*b0.y;
        acc.z += w0*a1.x + w1*b1.x; acc.w += w0*a1.y + w1*b1.y;
    }
    if(j < e){
        int r = arow[j]; float w = aw[j];
        uint2 u = *(const uint2*)(in + (size_t)r*HD + lane*4);
        float2 a0 = __half22float2(*(__half2*)&u.x);
        float2 a1 = __half22float2(*(__half2*)&u.y);
        acc.x += w*a0.x; acc.y += w*a0.y; acc.z += w*a1.x; acc.w += w*a1.y;
    }
    __half2 o0 = __floats2half2_rn(acc.x, acc.y);
    __half2 o1 = __floats2half2_rn(acc.z, acc.w);
    uint2 uo; uo.x = *(uint32_t*)&o0; uo.y = *(uint32_t*)&o1;
    *(uint2*)(out16 + (size_t)n*HD + lane*4) = uo;
}

// den'[n] = (dot(qn,ksum) + NN)/NN;  q16[n,:] = fp16(qn/den')
__global__ void den_scale(__half* __restrict__ q16, const float* __restrict__ ksum,
                          float* __restrict__ den){
    int n = blockIdx.x*8 + (threadIdx.x >> 5);
    if(n >= NN) return;
    int lane = threadIdx.x & 31;
    uint2 u = *(const uint2*)(q16 + (size_t)n*HD + lane*4);
    float2 v0 = __half22float2(*(__half2*)&u.x);
    float2 v1 = __half22float2(*(__half2*)&u.y);
    float4 k4 = ((const float4*)ksum)[lane];
    float d = v0.x*k4.x + v0.y*k4.y + v1.x*k4.z + v1.y*k4.w;
    #pragma unroll
    for(int o=16;o;o>>=1) d += __shfl_xor_sync(0xffffffffu, d, o);
    d += (float)NN;
    float dn = d * (1.0f/(float)NN);
    if(lane == 0) den[n] = dn;
    float inv = 1.f/dn;
    __half2 o0 = __floats2half2_rn(v0.x*inv, v0.y*inv);
    __half2 o1 = __floats2half2_rn(v1.x*inv, v1.y*inv);
    uint2 uo; uo.x = *(uint32_t*)&o0; uo.y = *(uint32_t*)&o1;
    *(uint2*)(q16 + (size_t)n*HD + lane*4) = uo;
}

// w0p16[n][m] = fp16( (kvs @ W0)[m][n] / NN ),  c0[n] = (vsum@W0)[n]/NN. Grid=129.
__global__ void kvs_w0(const float* __restrict__ kvs, const float* __restrict__ vsum,
                       const float* __restrict__ W0,
                       __half* __restrict__ W0p16, float* __restrict__ c0){
    int m = blockIdx.x;
    int j = threadIdx.x;
    const float* rowp = (m < HD) ? (kvs + (size_t)m*HD) : vsum;
    float s = 0.f;
    #pragma unroll 4
    for(int d = 0; d < HD; d++) s += rowp[d] * __ldg(W0 + (size_t)d*HD + j);
    s *= (1.0f/(float)NN);
    if(m < HD) W0p16[(size_t)j*HD + m] = __float2half_rn(s);
    else       c0[j] = s;
}

// ================= fp16 mma.m16n8k16 GEMM, cp.async double-buffered ====
// A parts: fp16 [row][128]. B parts: fp16 TRANSPOSED [n][128].
// MODE 3: C16 = fp16(rownorm(acc+v1)); cs[blk] = col partials
// MODE 5: C = acc + v1;                  cs/cq[blk]
// MODE 7: C16 = fp16(rownorm(acc+v1))
// MODE 8: C = acc + v1 + res16 + v2[col]/den[row]; cs/cq[blk]
struct PartsH  { const __half* p[5]; };
struct PartsBH { const __half* p[5]; };

#define SA0 0
#define SA1 10240
#define SB0 20480
#define SB1 30720
#define SM_TOTAL 40960

template<int NPARTS, int MODE>
__global__ __launch_bounds__(256, 2)
void sgemm_mma(PartsH parts, PartsBH bparts,
               const float* __restrict__ v1, const float* __restrict__ v2,
               float* den, const __half* __restrict__ res,
               float* __restrict__ C, __half* __restrict__ C16,
               float* __restrict__ cs, float* __restrict__ cq,
               int M){
    extern __shared__ char smem[];
    uint32_t sb = smem_u32(smem);
    int tid = threadIdx.x;
    int w = tid >> 5, lane = tid & 31;
    int g = lane >> 2, t = lane & 3;
    int m0 = (w & 3) * 32;
    int n0 = (w >> 2) * 64;
    int bm = blockIdx.x * 128;
    const int NCH = 4*NPARTS;

    float acc[2][8][4];
    #pragma unroll
    for(int mt=0;mt<2;mt++)
        #pragma unroll
        for(int nt=0;nt<8;nt++)
            #pragma unroll
            for(int i=0;i<4;i++) acc[mt][nt][i] = 0.f;

    auto prefetch = [&](int ch, int st){
        const __half* A  = parts.p[ch>>2];
        const __half* Bp = bparts.p[ch>>2];
        int kcc = ch & 3;
        uint32_t da = sb + (st ? SA1 : SA0);
        uint32_t db = sb + (st ? SB1 : SB0);
        // A tile: 128 rows x 32 halves (64B -> 4 x 16B per row)
        #pragma unroll
        for(int it=0; it<2; ++it){
            int idx = tid + it*256;       // 0..511
            int r = idx >> 2, c8 = idx & 3;
            int gr = bm + r;
            int grc = (gr < M) ? gr : (M-1);
            cp16(da + (uint32_t)(r*80 + c8*16),
                 A + (size_t)grc*HD + kcc*32 + c8*8, gr < M);
        }
        // B tile: 128 n-rows x 32 halves from transposed [n][128]
        #pragma unroll
        for(int it=0; it<2; ++it){
            int idx = tid + it*256;
            int r = idx >> 2, c8 = idx & 3;
            cp16(db + (uint32_t)(r*80 + c8*16),
                 Bp + (size_t)r*HD + kcc*32 + c8*8, true);
        }
    };

    prefetch(0, 0); CP_COMMIT();
    #pragma unroll 1
    for(int ch=0; ch<NCH; ++ch){
        int st = ch & 1;
        if(ch+1 < NCH){ prefetch(ch+1, st^1); CP_COMMIT(); CP_WAIT1(); }
        else CP_WAIT0();
        __syncthreads();
        const uint32_t* cA = (const uint32_t*)(smem + (st ? SA1 : SA0));
        const uint32_t* cB = (const uint32_t*)(smem + (st ? SB1 : SB0));
        #pragma unroll
        for(int ks=0; ks<2; ++ks){
            int kh = ks*8;                 // uint32 offset within 40-half row
            uint32_t a[2][4], b[8][2];
            #pragma unroll
            for(int mt=0;mt<2;mt++){
                int rb = m0 + mt*16 + g;
                a[mt][0] = cA[rb*20 + kh + t];
                a[mt][1] = cA[(rb+8)*20 + kh + t];
                a[mt][2] = cA[rb*20 + kh + t + 4];
                a[mt][3] = cA[(rb+8)*20 + kh + t + 4];
            }
            #pragma unroll
            for(int nt=0;nt<8;nt++){
                int nc = n0 + nt*8 + g;
                b[nt][0] = cB[nc*20 + kh + t];
                b[nt][1] = cB[nc*20 + kh + t + 4];
            }
            #pragma unroll
            for(int mt=0;mt<2;mt++){
                #pragma unroll
                for(int nt=0;nt<8;nt++){
                    asm volatile(
                        "mma.sync.aligned.m16n8k16.row.col.f32.f16.f16.f32 "
                        "{%0,%1,%2,%3}, {%4,%5,%6,%7}, {%8,%9}, {%0,%1,%2,%3};"
                        : "+f"(acc[mt][nt][0]), "+f"(acc[mt][nt][1]),
                          "+f"(acc[mt][nt][2]), "+f"(acc[mt][nt][3])
                        : "r"(a[mt][0]), "r"(a[mt][1]), "r"(a[mt][2]), "r"(a[mt][3]),
                          "r"(b[nt][0]), "r"(b[nt][1]));
                }
            }
        }
        __syncthreads();
    }

    // ---------- epilogue ----------
    float* sred  = (float*)smem;
    float* scol  = (float*)(smem + 2048);
    float* sqol  = (float*)(smem + 4096);

    float be[8][2];
    #pragma unroll
    for(int nt=0;nt<8;nt++){
        int c0i = n0 + nt*8 + 2*t;
        be[nt][0] = __ldg(v1 + c0i); be[nt][1] = __ldg(v1 + c0i + 1);
    }

    if(MODE == 3 || MODE == 7){
        float ss[2][2] = {{0.f,0.f},{0.f,0.f}};
        #pragma unroll
        for(int mt=0;mt<2;mt++){
            #pragma unroll
            for(int nt=0;nt<8;nt++){
                float o0 = acc[mt][nt][0] + be[nt][0];
                float o1 = acc[mt][nt][1] + be[nt][1];
                float o2 = acc[mt][nt][2] + be[nt][0];
                float o3 = acc[mt][nt][3] + be[nt][1];
                acc[mt][nt][0]=o0; acc[mt][nt][1]=o1; acc[mt][nt][2]=o2; acc[mt][nt][3]=o3;
                ss[mt][0] += o0*o0 + o1*o1;
                ss[mt][1] += o2*o2 + o3*o3;
            }
        }
        #pragma unroll
        for(int off=1; off<=2; off<<=1){
            #pragma unroll
            for(int mt=0;mt<2;mt++){
                ss[mt][0] += __shfl_xor_sync(0xffffffffu, ss[mt][0], off);
                ss[mt][1] += __shfl_xor_sync(0xffffffffu, ss[mt][1], off);
            }
        }
        int half = w >> 2;
        if(t == 0){
            #pragma unroll
            for(int mt=0;mt<2;mt++){
                sred[half*128 + m0 + mt*16 + g]     = ss[mt][0];
                sred[half*128 + m0 + mt*16 + g + 8] = ss[mt][1];
            }
        }
        __syncthreads();
        float inv[2][2];
        #pragma unroll
        for(int mt=0;mt<2;mt++){
            #pragma unroll
            for(int j=0;j<2;j++){
                int rl = m0 + mt*16 + g + j*8;
                inv[mt][j] = rsqrtf(sred[rl] + sred[128 + rl]);
            }
        }
        float ca[8][2];
        #pragma unroll
        for(int nt=0;nt<8;nt++){ ca[nt][0]=0.f; ca[nt][1]=0.f; }
        #pragma unroll
        for(int mt=0;mt<2;mt++){
            int r1 = bm + m0 + mt*16 + g, r2 = r1 + 8;
            bool ok1 = r1 < M, ok2 = r2 < M;
            #pragma unroll
            for(int nt=0;nt<8;nt++){
                int cc = n0 + nt*8 + 2*t;
                __half2 p0 = __floats2half2_rn(acc[mt][nt][0]*inv[mt][0],
                                               acc[mt][nt][1]*inv[mt][0]);
                __half2 p1 = __floats2half2_rn(acc[mt][nt][2]*inv[mt][1],
                                               acc[mt][nt][3]*inv[mt][1]);
                if(ok1) *(uint32_t*)(C16 + (size_t)r1*HD + cc) = *(uint32_t*)&p0;
                if(ok2) *(uint32_t*)(C16 + (size_t)r2*HD + cc) = *(uint32_t*)&p1;
                if(MODE == 3){
                    float2 f0 = __half22float2(p0);
                    float2 f1 = __half22float2(p1);
                    ca[nt][0] += (ok1?f0.x:0.f) + (ok2?f1.x:0.f);
                    ca[nt][1] += (ok1?f0.y:0.f) + (ok2?f1.y:0.f);
                }
            }
        }
        if(MODE == 3){
            #pragma unroll
            for(int off=4; off<=16; off<<=1)
                #pragma unroll
                for(int nt=0;nt<8;nt++){
                    ca[nt][0] += __shfl_xor_sync(0xffffffffu, ca[nt][0], off);
                    ca[nt][1] += __shfl_xor_sync(0xffffffffu, ca[nt][1], off);
                }
            if(lane < 4){
                #pragma unroll
                for(int nt=0;nt<8;nt++){
                    scol[w*64 + nt*8 + 2*t]     = ca[nt][0];
                    scol[w*64 + nt*8 + 2*t + 1] = ca[nt][1];
                }
            }
            __syncthreads();
            if(tid < 128){
                int c = tid, hf = c >> 6, cl = c & 63;
                float s = 0.f;
                #pragma unroll
                for(int j=0;j<4;j++) s += scol[(hf*4+j)*64 + cl];
                cs[blockIdx.x*HD + c] = s;
            }
        }
    } else { // MODE 5 / 8
        float ce[8][2];
        if(MODE == 8){
            #pragma unroll
            for(int nt=0;nt<8;nt++){
                int c0i = n0 + nt*8 + 2*t;
                ce[nt][0] = __ldg(v2 + c0i); ce[nt][1] = __ldg(v2 + c0i + 1);
            }
        }
        float ca[8][2], cqv[8][2];
        #pragma unroll
        for(int nt=0;nt<8;nt++){ ca[nt][0]=0.f; ca[nt][1]=0.f; cqv[nt][0]=0.f; cqv[nt][1]=0.f; }
        #pragma unroll
        for(int mt=0;mt<2;mt++){
            int r1 = bm + m0 + mt*16 + g, r2 = r1 + 8;
            bool ok1 = r1 < M, ok2 = r2 < M;
            float i1 = 0.f, i2 = 0.f;
            if(MODE == 8){
                if(ok1) i1 = 1.f/den[r1];
                if(ok2) i2 = 1.f/den[r2];
            }
            #pragma unroll
            for(int nt=0;nt<8;nt++){
                int cc = n0 + nt*8 + 2*t;
                float o0 = acc[mt][nt][0] + be[nt][0];
                float o1 = acc[mt][nt][1] + be[nt][1];
                float o2 = acc[mt][nt][2] + be[nt][0];
                float o3 = acc[mt][nt][3] + be[nt][1];
                if(MODE == 8){
                    o0 += ce[nt][0]*i1; o1 += ce[nt][1]*i1;
                    o2 += ce[nt][0]*i2; o3 += ce[nt][1]*i2;
                    if(ok1){
                        uint32_t rv = *(const uint32_t*)(res + (size_t)r1*HD + cc);
                        float2 rf = __half22float2(*(__half2*)&rv);
                        o0 += rf.x; o1 += rf.y;
                    }
                    if(ok2){
                        uint32_t rv = *(const uint32_t*)(res + (size_t)r2*HD + cc);
                        float2 rf = __half22float2(*(__half2*)&rv);
                        o2 += rf.x; o3 += rf.y;
                    }
                }
                if(ok1) *(float2*)(C + (size_t)r1*HD + cc) = make_float2(o0, o1);
                if(ok2) *(float2*)(C + (size_t)r2*HD + cc) = make_float2(o2, o3);
                ca[nt][0]  += (ok1?o0:0.f) + (ok2?o2:0.f);
                ca[nt][1]  += (ok1?o1:0.f) + (ok2?o3:0.f);
                cqv[nt][0] += (ok1?o0*o0:0.f) + (ok2?o2*o2:0.f);
                cqv[nt][1] += (ok1?o1*o1:0.f) + (ok2?o3*o3:0.f);
            }
        }
        #pragma unroll
        for(int off=4; off<=16; off<<=1)
            #pragma unroll
            for(int nt=0;nt<8;nt++){
                ca[nt][0]  += __shfl_xor_sync(0xffffffffu, ca[nt][0], off);
                ca[nt][1]  += __shfl_xor_sync(0xffffffffu, ca[nt][1], off);
                cqv[nt][0] += __shfl_xor_sync(0xffffffffu, cqv[nt][0], off);
                cqv[nt][1] += __shfl_xor_sync(0xffffffffu, cqv[nt][1], off);
            }
        if(lane < 4){
            #pragma unroll
            for(int nt=0;nt<8;nt++){
                scol[w*64 + nt*8 + 2*t]     = ca[nt][0];
                scol[w*64 + nt*8 + 2*t + 1] = ca[nt][1];
                sqol[w*64 + nt*8 + 2*t]     = cqv[nt][0];
                sqol[w*64 + nt*8 + 2*t + 1] = cqv[nt][1];
            }
        }
        __syncthreads();
        if(tid < 128){
            int c = tid, hf = c >> 6, cl = c & 63;
            float s = 0.f, qq = 0.f;
            #pragma unroll
            for(int j=0;j<4;j++){ s += scol[(hf*4+j)*64 + cl]; qq += sqol[(hf*4+j)*64 + cl]; }
            cs[blockIdx.x*HD + c] = s;
            cq[blockIdx.x*HD + c] = qq;
        }
    }
}

// ================= kvs via tensor cores (tf32; fp16 inputs cvt on smem fill) ======
#define KV_SA 0
#define KV_SB 34816
#define KV_SMEM 69632

__global__ __launch_bounds__(256, 2)
void kvs_mma(const __half* __restrict__ kn, const __half* __restrict__ vv,
             float* __restrict__ part){
    extern __shared__ char smem[];
    float* sA = (float*)(smem + KV_SA);
    float* sB = (float*)(smem + KV_SB);
    int tid = threadIdx.x;
    int w = tid >> 5, lane = tid & 31;
    int g = lane >> 2, t = lane & 3;
    int m0 = (w & 3) * 32;
    int n0 = (w >> 2) * 64;
    int base = blockIdx.x * 256;

    float acc[2][8][4];
    #pragma unroll
    for(int mt=0;mt<2;mt++)
        #pragma unroll
        for(int nt=0;nt<8;nt++)
            #pragma unroll
            for(int i=0;i<4;i++) acc[mt][nt][i] = 0.f;

    #pragma unroll 1
    for(int sub=0; sub<4; ++sub){
        int nb = base + sub*64;
        #pragma unroll
        for(int it=0; it<8; ++it){
            int idx = tid + it*256;
            int r = idx >> 5, c4 = idx & 31;
            int gn = nb + r;
            float4 ka = make_float4(0,0,0,0), va = make_float4(0,0,0,0);
            if(gn < NN){
                uint2 uk = *(const uint2*)(kn + (size_t)gn*HD + c4*4);
                uint2 uv = *(const uint2*)(vv + (size_t)gn*HD + c4*4);
                float2 k0 = __half22float2(*(__half2*)&uk.x);
                float2 k1 = __half22float2(*(__half2*)&uk.y);
                float2 v0 = __half22float2(*(__half2*)&uv.x);
                float2 v1 = __half22float2(*(__half2*)&uv.y);
                ka = make_float4(k0.x,k0.y,k1.x,k1.y);
                va = make_float4(v0.x,v0.y,v1.x,v1.y);
            }
            *(float4*)(sA + r*136 + c4*4) = ka;
            *(float4*)(sB + r*136 + c4*4) = va;
        }
        __syncthreads();
        #pragma unroll
        for(int ks=0; ks<8; ++ks){
            int k0 = ks*8;
            uint32_t a[2][4], b[8][2];
            const uint32_t* uA = (const uint32_t*)sA;
            const uint32_t* uB = (const uint32_t*)sB;
            #pragma unroll
            for(int mt=0;mt<2;mt++){
                int rb = m0 + mt*16 + g;
                a[mt][0] = uA[(k0+t)*136 + rb];
                a[mt][1] = uA[(k0+t)*136 + rb + 8];
                a[mt][2] = uA[(k0+t+4)*136 + rb];
                a[mt][3] = uA[(k0+t+4)*136 + rb + 8];
            }
            #pragma unroll
            for(int nt=0;nt<8;nt++){
                int nc = n0 + nt*8 + g;
                b[nt][0] = uB[(k0+t)*136 + nc];
                b[nt][1] = uB[(k0+t+4)*136 + nc];
            }
            #pragma unroll
            for(int mt=0;mt<2;mt++){
                #pragma unroll
                for(int nt=0;nt<8;nt++){
                    asm volatile(
                        "mma.sync.aligned.m16n8k8.row.col.f32.tf32.tf32.f32 "
                        "{%0,%1,%2,%3}, {%4,%5,%6,%7}, {%8,%9}, {%0,%1,%2,%3};"
                        : "+f"(acc[mt][nt][0]), "+f"(acc[mt][nt][1]),
                          "+f"(acc[mt][nt][2]), "+f"(acc[mt][nt][3])
                        : "r"(a[mt][0]), "r"(a[mt][1]), "r"(a[mt][2]), "r"(a[mt][3]),
                          "r"(b[nt][0]), "r"(b[nt][1]));
                }
            }
        }
        __syncthreads();
    }

    float* P = part + (size_t)blockIdx.x*HD*HD;
    #pragma unroll
    for(int mt=0;mt<2;mt++){
        int r1 = m0 + mt*16 + g;
        int r2 = r1 + 8;
        #pragma unroll
        for(int nt=0;nt<8;nt++){
            int cc = n0 + nt*8 + 2*t;
            *(float2*)(P + (size_t)r1*HD + cc) = make_float2(acc[mt][nt][0], acc[mt][nt][1]);
            *(float2*)(P + (size_t)r2*HD + cc) = make_float2(acc[mt][nt][2], acc[mt][nt][3]);
        }
    }
}

__global__ void kvs_reduce(const float* __restrict__ part, float* __restrict__ kvs){
    int i = blockIdx.x*blockDim.x + threadIdx.x;
    if(i >= HD*HD) return;
    float s = 0.f;
    for(int b=0;b<KVB2;b++) s += part[(size_t)b*HD*HD + i];
    kvs[i] = s;
}

// ================= parallel small reductions =================
__global__ void colsum_reduce(const float* __restrict__ part, float* __restrict__ out,
                              int count){
    __shared__ float sh[8][128];
    int c = threadIdx.x & 127, sl = threadIdx.x >> 7;
    float s = 0.f;
    for(int b = sl; b < count; b += 8) s += part[b*HD + c];
    sh[sl][c] = s;
    __syncthreads();
    if(threadIdx.x < 128){
        float tot = 0.f;
        #pragma unroll
        for(int j=0;j<8;j++) tot += sh[j][c];
        out[c] = tot;
    }
}

__global__ void bn_finish(const float* __restrict__ ps, const float* __restrict__ pq,
                          const float* __restrict__ g, const float* __restrict__ b,
                          float* __restrict__ scale, float* __restrict__ shift,
                          int count){
    __shared__ float shs[8][128], shq[8][128];
    int c = threadIdx.x & 127, sl = threadIdx.x >> 7;
    float s = 0.f, q = 0.f;
    for(int i = sl; i < count; i += 8){ s += ps[i*HD+c]; q += pq[i*HD+c]; }
    shs[sl][c] = s; shq[sl][c] = q;
    __syncthreads();
    if(threadIdx.x < 128){
        float ts = 0.f, tq = 0.f;
        #pragma unroll
        for(int j=0;j<8;j++){ ts += shs[j][c]; tq += shq[j][c]; }
        float mean = ts / (float)NN;
        float var  = tq / (float)NN - mean*mean;
        float sc = g[c] * rsqrtf(var + EPSI);
        scale[c] = sc;
        shift[c] = b[c] - mean*sc;
    }
}

// BN apply + relu; writes fp16 h16 and column partial sums of the rounded values
__global__ void bn_apply_relu(const float* __restrict__ z, const float* __restrict__ scale,
                              const float* __restrict__ shift,
                              __half* __restrict__ h16, float* __restrict__ hpart){
    int c = threadIdx.x;
    int b = blockIdx.x;
    int chunk = (NN + BAP - 1)/BAP;
    int r0 = b*chunk, r1 = min(NN, r0 + chunk);
    float sc = scale[c], sh = shift[c];
    float s = 0.f;
    for(int r = r0; r < r1; ++r){
        float raw = fmaxf(z[(size_t)r*HD + c]*sc + sh, 0.f);
        __half hv = __float2half_rn(raw);
        h16[(size_t)r*HD + c] = hv;
        s += __half2float(hv);
    }
    hpart[b*HD + c] = s;
}

__global__ void out_gemm(const __half* __restrict__ h16, const float* __restrict__ W,
                         const float* __restrict__ b, float* __restrict__ out){
    int n = blockIdx.x*8 + (threadIdx.x >> 5);
    if(n >= NN) return;
    int lane = threadIdx.x & 31;
    const __half* hr = h16 + (size_t)n*HD;
    float acc0 = 0.f, acc1 = 0.f;
    #pragma unroll 8
    for(int k4=0;k4<32;k4++){
        uint2 u = *(const uint2*)(hr + k4*4);
        float2 a0 = __half22float2(*(__half2*)&u.x);
        float2 a1 = __half22float2(*(__half2*)&u.y);
        int k = k4*4;
        acc0 += a0.x*__ldg(W + (k+0)*40 + lane);
        acc0 += a0.y*__ldg(W + (k+1)*40 + lane);
        acc0 += a1.x*__ldg(W + (k+2)*40 + lane);
        acc0 += a1.y*__ldg(W + (k+3)*40 + lane);
        if(lane < 8){
            acc1 += a0.x*__ldg(W + (k+0)*40 + 32 + lane);
            acc1 += a0.y*__ldg(W + (k+1)*40 + 32 + lane);
            acc1 += a1.x*__ldg(W + (k+2)*40 + 32 + lane);
            acc1 += a1.y*__ldg(W + (k+3)*40 + 32 + lane);
        }
    }
    out[(size_t)n*40 + lane] = acc0 + b[lane];
    if(lane < 8) out[(size_t)n*40 + 32 + lane] = acc1 + b[32 + lane];
}

// ================= host =================
extern "C" void kernel_launch(void* const* d_in, const int* in_sizes, int n_in,
                              void* d_out, int out_size){
    const float* x     = (const float*)d_in[0];
    const int*   ei    = (const int*)  d_in[1];
    const float* W_in  = (const float*)d_in[2];
    const float* b_in  = (const float*)d_in[3];
    const float* Wq    = (const float*)d_in[4];
    const float* bq    = (const float*)d_in[5];
    const float* Wk    = (const float*)d_in[6];
    const float* bk    = (const float*)d_in[7];
    const float* Wfc   = (const float*)d_in[8];
    const float* bfc   = (const float*)d_in[9];
    const float* W_out = (const float*)d_in[10];
    const float* b_out = (const float*)d_in[11];
    const float* bn_g  = (const float*)d_in[12];
    const float* bn_b  = (const float*)d_in[13];
    float* out = (float*)d_out;

    const int* row = ei;
    const int* col = ei + EE;

    float *z,*kvspart,*kvs,*c0,*hpart,*kpart,*bns,*bnq;
    float *ksum,*vsum,*scale,*shift,*den,*dis,*aw;
    __half *h16,*x16,*q16,*k16,*pa16,*pb16,*pc16,*w0p16,*wt16;
    int *deg,*indptr,*cursor,*arow;
    cudaGetSymbolAddress((void**)&z,  g_z);
    cudaGetSymbolAddress((void**)&h16, g_h16);
    cudaGetSymbolAddress((void**)&x16, g_x16);
    cudaGetSymbolAddress((void**)&q16, g_q16);
    cudaGetSymbolAddress((void**)&k16, g_k16);
    cudaGetSymbolAddress((void**)&pa16, g_pa16);
    cudaGetSymbolAddress((void**)&pb16, g_pb16);
    cudaGetSymbolAddress((void**)&pc16, g_pc16);
    cudaGetSymbolAddress((void**)&kvspart, g_kvspart);
    cudaGetSymbolAddress((void**)&kvs, g_kvs);
    cudaGetSymbolAddress((void**)&w0p16, g_w0p16);
    cudaGetSymbolAddress((void**)&c0,  g_c0);
    cudaGetSymbolAddress((void**)&wt16, g_wt16);
    cudaGetSymbolAddress((void**)&hpart, g_hpart);
    cudaGetSymbolAddress((void**)&kpart, g_kpart);
    cudaGetSymbolAddress((void**)&bns, g_bns);
    cudaGetSymbolAddress((void**)&bnq, g_bnq);
    cudaGetSymbolAddress((void**)&ksum, g_ksum);
    cudaGetSymbolAddress((void**)&vsum, g_vsum);
    cudaGetSymbolAddress((void**)&scale, g_scale);
    cudaGetSymbolAddress((void**)&shift, g_shift);
    cudaGetSymbolAddress((void**)&den, g_den);
    cudaGetSymbolAddress((void**)&dis, g_dis);
    cudaGetSymbolAddress((void**)&aw,  g_aw);
    cudaGetSymbolAddress((void**)&deg, g_deg);
    cudaGetSymbolAddress((void**)&indptr, g_indptr);
    cudaGetSymbolAddress((void**)&cursor, g_cursor);
    cudaGetSymbolAddress((void**)&arow, g_arow);

    const __half* wtWin = wt16;
    const __half* wtWq  = wt16 + 16384;
    const __half* wtWk  = wt16 + 49152;
    const __half* wtWfc = wt16 + 81920;

    cudaFuncSetAttribute(sgemm_mma<1,3>, cudaFuncAttributeMaxDynamicSharedMemorySize, SM_TOTAL);
    cudaFuncSetAttribute(sgemm_mma<1,5>, cudaFuncAttributeMaxDynamicSharedMemorySize, SM_TOTAL);
    cudaFuncSetAttribute(sgemm_mma<1,7>, cudaFuncAttributeMaxDynamicSharedMemorySize, SM_TOTAL);
    cudaFuncSetAttribute(sgemm_mma<5,8>, cudaFuncAttributeMaxDynamicSharedMemorySize, SM_TOTAL);
    cudaFuncSetAttribute(kvs_mma, cudaFuncAttributeMaxDynamicSharedMemorySize, KV_SMEM);

    const int WARP_GRID = (NN + 7)/8;

    static cudaStream_t s1 = nullptr, s2 = nullptr;
    static cudaEvent_t e0, e1, eF[2], eK[2], eS1[2], eQ[2];
    if(s1 == nullptr){
        cudaStreamCreateWithFlags(&s1, cudaStreamNonBlocking);
        cudaStreamCreateWithFlags(&s2, cudaStreamNonBlocking);
        cudaEventCreateWithFlags(&e0, cudaEventDisableTiming);
        cudaEventCreateWithFlags(&e1, cudaEventDisableTiming);
        for(int i=0;i<2;i++){
            cudaEventCreateWithFlags(&eF[i],  cudaEventDisableTiming);
            cudaEventCreateWithFlags(&eK[i],  cudaEventDisableTiming);
            cudaEventCreateWithFlags(&eS1[i], cudaEventDisableTiming);
            cudaEventCreateWithFlags(&eQ[i],  cudaEventDisableTiming);
        }
    }

    // ---- fork: graph preprocessing on s1; conversions + input layer on stream 0 ----
    cudaEventRecord(e0, 0);
    cudaStreamWaitEvent(s1, e0, 0);
    cudaMemsetAsync(deg, 0, NN*sizeof(int), s1);
    deg_count<<<(EE+255)/256, 256, 0, s1>>>(col, deg);
    dis_kernel<<<(NN+255)/256, 256, 0, s1>>>(deg, dis);
    scan_kernel<<<1, 1024, 0, s1>>>(deg, indptr, cursor);
    csr_fill<<<(EE+255)/256, 256, 0, s1>>>(row, col, dis, cursor, arow, aw);
    cudaEventRecord(e1, s1);

    cvt_weights16<<<(15*16384+255)/256, 256>>>(W_in, Wq, Wk, Wfc, wt16);
    cvt_x16<<<(NN*HD+255)/256, 256>>>(x, x16);
    {
        PartsH P; P.p[0]=x16; P.p[1]=0; P.p[2]=0; P.p[3]=0; P.p[4]=0;
        PartsBH B; B.p[0]=wtWin; B.p[1]=0; B.p[2]=0; B.p[3]=0; B.p[4]=0;
        sgemm_mma<1,5><<<TCG,256,SM_TOTAL>>>(P, B, b_in, nullptr, nullptr, nullptr,
                                             z, nullptr, bns, bnq, NN);
        bn_finish<<<1,1024>>>(bns, bnq, bn_g + 0*HD, bn_b + 0*HD, scale, shift, TCG);
        bn_apply_relu<<<BAP,HD>>>(z, scale, shift, h16, hpart);
    }

    for(int i=0;i<2;i++){
        PartsH Ph; Ph.p[0]=h16; Ph.p[1]=0; Ph.p[2]=0; Ph.p[3]=0; Ph.p[4]=0;
        const float* Wfci = Wfc + (size_t)i*640*HD;              // original (for kvs_w0)
        const __half* wtWfci = wtWfc + (size_t)i*640*HD;         // fp16 transposed

        cudaEventRecord(eF[i], 0);
        cudaStreamWaitEvent(s1, eF[i], 0);
        cudaStreamWaitEvent(s2, eF[i], 0);

        // ---- s1: vsum, k-GEMM -> ksum -> kvs -> W0p/c0 ----
        colsum_reduce<<<1,1024,0,s1>>>(hpart, vsum, BAP);
        {
            PartsBH Bk; Bk.p[0]=wtWk + (size_t)i*HD*HD; Bk.p[1]=0; Bk.p[2]=0; Bk.p[3]=0; Bk.p[4]=0;
            sgemm_mma<1,3><<<TCG,256,SM_TOTAL,s1>>>(Ph, Bk, bk + i*HD, nullptr, nullptr,
                                                    nullptr, nullptr, k16, kpart, nullptr, NN);
        }
        colsum_reduce<<<1,1024,0,s1>>>(kpart, ksum, TCG);
        cudaEventRecord(eK[i], s1);
        kvs_mma<<<KVB2,256,KV_SMEM,s1>>>(k16, h16, kvspart);
        kvs_reduce<<<(HD*HD+255)/256,256,0,s1>>>(kvspart, kvs);
        kvs_w0<<<HD+1,HD,0,s1>>>(kvs, vsum, Wfci, w0p16, c0);
        cudaEventRecord(eS1[i], s1);

        // ---- s2: q-GEMM (norm only) -> den' + row scale ----
        {
            PartsBH Bq; Bq.p[0]=wtWq + (size_t)i*HD*HD; Bq.p[1]=0; Bq.p[2]=0; Bq.p[3]=0; Bq.p[4]=0;
            sgemm_mma<1,7><<<TCG,256,SM_TOTAL,s2>>>(Ph, Bq, bq + i*HD, nullptr, nullptr,
                                                    nullptr, nullptr, q16, nullptr, nullptr, NN);
        }
        cudaStreamWaitEvent(s2, eK[i], 0);
        den_scale<<<WARP_GRID,256,0,s2>>>(q16, ksum, den);
        cudaEventRecord(eQ[i], s2);

        // ---- s0: prop chain (fp16) ----
        if(i == 0) cudaStreamWaitEvent(0, e1, 0);
        prop16<<<WARP_GRID,256>>>(indptr, arow, aw, h16,  pa16);
        prop16<<<WARP_GRID,256>>>(indptr, arow, aw, pa16, pb16);
        prop16<<<WARP_GRID,256>>>(indptr, arow, aw, pb16, pc16);

        // ---- join: Wfc 5-part with W0p substitution (+BN partials) ----
        cudaStreamWaitEvent(0, eS1[i], 0);
        cudaStreamWaitEvent(0, eQ[i], 0);
        {
            PartsH P5; P5.p[0]=q16; P5.p[1]=h16; P5.p[2]=pa16; P5.p[3]=pb16; P5.p[4]=pc16;
            PartsBH B5; B5.p[0]=w0p16;
            B5.p[1]=wtWfci + 1*HD*HD; B5.p[2]=wtWfci + 2*HD*HD;
            B5.p[3]=wtWfci + 3*HD*HD; B5.p[4]=wtWfci + 4*HD*HD;
            sgemm_mma<5,8><<<TCG,256,SM_TOTAL>>>(P5, B5, bfc + i*HD, c0, den, h16,
                                                 z, nullptr, bns, bnq, NN);
        }
        bn_finish<<<1,1024>>>(bns, bnq, bn_g + (i+1)*HD, bn_b + (i+1)*HD, scale, shift, TCG);
        bn_apply_relu<<<BAP,HD>>>(z, scale, shift, h16, hpart);
    }

    out_gemm<<<WARP_GRID,256>>>(h16, W_out, b_out, out);
}